// round 5
// baseline (speedup 1.0000x reference)
#include <cuda_runtime.h>
#include <cuda_bf16.h>
#include <cstdint>

// ---------------- problem constants ----------------
#define BB   8
#define NR   4096
#define NK   20
#define FF   256
#define HH   4
#define KH   80
#define KNN  8

// ---------------- device scratch ----------------
__device__ float g_ftdst[BB * NK * 1024];
__device__ float g_V[BB * FF * KH];
__device__ float g_S[BB * NK * HH * 4];

// ---------------- f32x2 helpers ----------------
__device__ __forceinline__ unsigned long long pack2(float x, float y) {
    unsigned long long r;
    asm("mov.b64 %0, {%1, %2};" : "=l"(r) : "f"(x), "f"(y));
    return r;
}
__device__ __forceinline__ void unpack2(unsigned long long v, float& x, float& y) {
    asm("mov.b64 {%0, %1}, %2;" : "=f"(x), "=f"(y) : "l"(v));
}
__device__ __forceinline__ void fma2(unsigned long long& d, unsigned long long a, unsigned long long b) {
    asm("fma.rn.f32x2 %0, %1, %2, %0;" : "+l"(d) : "l"(a), "l"(b));
}

// ---------------- A1: ft_dst = h0_kp @ W_src ----------------
#define FT_SMEM_FLOATS (NK * FF + 256 * 65)
__global__ void __launch_bounds__(256) k_ftdst(const float* __restrict__ h0,
                                               const float* __restrict__ W) {
    extern __shared__ float sm[];
    float* hs = sm;
    float* ws = sm + NK * FF;
    int b = blockIdx.y, ct = blockIdx.x;
    if (ct == 0) {
        for (int i = threadIdx.x; i < FF * KH; i += 256) g_V[b * FF * KH + i] = 0.f;
    }
    for (int i = threadIdx.x; i < NK * FF; i += 256) hs[i] = h0[b * NK * FF + i];
#pragma unroll 8
    for (int i = threadIdx.x; i < 256 * 64; i += 256) {
        int f = i >> 6, c = i & 63;
        ws[f * 65 + c] = W[f * 1024 + ct * 64 + c];
    }
    __syncthreads();
    int cg = threadIdx.x & 63;
    int rgp = threadIdx.x >> 6;
    float acc[5] = {0.f, 0.f, 0.f, 0.f, 0.f};
#pragma unroll 8
    for (int f = 0; f < 256; f++) {
        float w = ws[f * 65 + cg];
#pragma unroll
        for (int q = 0; q < 5; q++) acc[q] += hs[(rgp * 5 + q) * 256 + f] * w;
    }
    int c = ct * 64 + cg;
#pragma unroll
    for (int q = 0; q < 5; q++)
        g_ftdst[(b * NK + rgp * 5 + q) * 1024 + c] = acc[q];
}

// ---------------- A2: V reduction ----------------
#define V_SMEM_FLOATS (64 * 257 + NK * 256)
__global__ void __launch_bounds__(256) k_V(const float* __restrict__ W) {
    extern __shared__ float sm[];
    float* ws2 = sm;
    float* fts2 = sm + 64 * 257;
    int b = blockIdx.y;
    int ft = blockIdx.x >> 2, ds = blockIdx.x & 3;
    int fbase = ft * 64, dbase = ds * 64;
#pragma unroll 4
    for (int i = threadIdx.x; i < 64 * 256; i += 256) {
        int fi = i >> 8, rest = i & 255;
        int h = rest >> 6, dd = rest & 63;
        ws2[fi * 257 + rest] = W[(fbase + fi) * 1024 + h * 256 + dbase + dd];
    }
#pragma unroll 4
    for (int i = threadIdx.x; i < NK * 256; i += 256) {
        int rest = i & 255;
        int h = rest >> 6, dd = rest & 63;
        int k = i >> 8;
        fts2[i] = g_ftdst[b * 20480 + k * 1024 + h * 256 + dbase + dd];
    }
    __syncthreads();
    int fi = threadIdx.x & 63;
    int h  = threadIdx.x >> 6;
    float acc[NK];
#pragma unroll
    for (int j = 0; j < NK; j++) acc[j] = 0.f;
    const float* wp = ws2 + fi * 257 + h * 64;
    const float* fp = fts2 + h * 64;
#pragma unroll 2
    for (int dd = 0; dd < 64; dd++) {
        float w = wp[dd];
#pragma unroll
        for (int j = 0; j < NK; j++) acc[j] += w * fp[j * 256 + dd];
    }
    float* gv = g_V + b * (FF * KH) + (fbase + fi) * KH + h;
#pragma unroll
    for (int j = 0; j < NK; j++)
        atomicAdd(gv + j * 4, acc[j] * 0.0625f);
}

// ---------------- zero g_S ----------------
__global__ void k_zeroS() {
    int i = blockIdx.x * blockDim.x + threadIdx.x;
    if (i < BB * NK * HH * 4) g_S[i] = 0.f;
}

// ---------------- B: fused  a = h_rec @ V ; exp ; 4 moments ----------------
// grid (32, 8) = 256 blocks, 256 threads, 2 CTAs/SM. 128 rows per CTA.
// Thread tile: 4 rows x 5 column-pairs. 3 LDS feed 20 fma2 per f.
#define ATTN_VS   (256 * 96)
#define ATTN_RED  2560
#define ATTN_SMEM_FLOATS (ATTN_VS + ATTN_RED)
__global__ void __launch_bounds__(256, 2) k_attn(const float* __restrict__ h_rec,
                                                 const float* __restrict__ x_rec) {
    extern __shared__ float sm[];
    float* Vsp = sm;
    float* red = sm + ATTN_VS;
    int b = blockIdx.y;
    int tid = threadIdx.x;
    int lane = tid & 31, w = tid >> 5;
    int rg = tid >> 3, cg = tid & 7;

    const float* gV = g_V + b * (FF * KH);
    for (int t = tid; t < FF * KH; t += 256) {
        int f = t / 80, q = t % 80;
        int c2 = q / 10, j = q % 10;
        int ip = j >> 1, sub = j & 1;
        int c = ((c2 + 8 * ip) << 1) | sub;
        Vsp[f * 96 + c2 * 12 + j] = gV[f * 80 + c];
    }
    for (int t = tid; t < ATTN_RED; t += 256) red[t] = 0.f;
    __syncthreads();

    int rowbase = blockIdx.x * 128;
    int row0 = rowbase + rg * 4;                        // 4 rows per thread
    const float4* hp = (const float4*)(h_rec + ((size_t)b * NR + row0) * FF);

    unsigned long long acc[4][5];
#pragma unroll
    for (int r = 0; r < 4; r++)
#pragma unroll
        for (int i = 0; i < 5; i++) acc[r][i] = 0ull;

    const char* vbase = (const char*)(Vsp + cg * 12);
    float4 a[4], n[4];
#pragma unroll
    for (int r = 0; r < 4; r++) a[r] = __ldg(hp + r * 64);
#pragma unroll 2
    for (int f4 = 0; f4 < 64; f4++) {
        if (f4 < 63) {
#pragma unroll
            for (int r = 0; r < 4; r++) n[r] = __ldg(hp + r * 64 + f4 + 1);
        }
#pragma unroll
        for (int e = 0; e < 4; e++) {
            const ulonglong2* vp = (const ulonglong2*)(vbase + (size_t)(f4 * 4 + e) * 384);
            ulonglong2 v01 = vp[0];
            ulonglong2 v23 = vp[1];
            unsigned long long v4 = *(const unsigned long long*)(vp + 2);
#pragma unroll
            for (int r = 0; r < 4; r++) {
                float h = (e == 0) ? a[r].x : (e == 1) ? a[r].y : (e == 2) ? a[r].z : a[r].w;
                unsigned long long H = pack2(h, h);
                fma2(acc[r][0], H, v01.x);
                fma2(acc[r][1], H, v01.y);
                fma2(acc[r][2], H, v23.x);
                fma2(acc[r][3], H, v23.y);
                fma2(acc[r][4], H, v4);
            }
        }
#pragma unroll
        for (int r = 0; r < 4; r++) a[r] = n[r];
    }

    // epilogue: exp + 4 moments over this thread's 4 rows
    const float* xp = x_rec + ((size_t)b * NR + row0) * 3;
    float xr[4][3];
#pragma unroll
    for (int r = 0; r < 4; r++) {
        xr[r][0] = xp[r * 3 + 0];
        xr[r][1] = xp[r * 3 + 1];
        xr[r][2] = xp[r * 3 + 2];
    }
#pragma unroll
    for (int i = 0; i < 5; i++) {
        float al[4], ah[4];
#pragma unroll
        for (int r = 0; r < 4; r++) unpack2(acc[r][i], al[r], ah[r]);
#pragma unroll
        for (int sub = 0; sub < 2; sub++) {
            float v0 = 0.f, v1 = 0.f, v2 = 0.f, v3 = 0.f;
#pragma unroll
            for (int r = 0; r < 4; r++) {
                float e = expf(sub ? ah[r] : al[r]);
                v0 += e;
                v1 += e * xr[r][0];
                v2 += e * xr[r][1];
                v3 += e * xr[r][2];
            }
#pragma unroll
            for (int d = 16; d >= 8; d >>= 1) {
                v0 += __shfl_down_sync(0xffffffffu, v0, d);
                v1 += __shfl_down_sync(0xffffffffu, v1, d);
                v2 += __shfl_down_sync(0xffffffffu, v2, d);
                v3 += __shfl_down_sync(0xffffffffu, v3, d);
            }
            if (lane < 8) {
                float* rp = red + w * 320 + cg * 40 + (2 * i + sub) * 4;
                rp[0] += v0; rp[1] += v1; rp[2] += v2; rp[3] += v3;
            }
        }
    }
    __syncthreads();
    for (int v = tid; v < 320; v += 256) {
        int cg2 = v / 40, sidx = v % 40;
        float sum = 0.f;
#pragma unroll
        for (int w2 = 0; w2 < 8; w2++) sum += red[w2 * 320 + cg2 * 40 + sidx];
        int pair = sidx >> 2, stat = sidx & 3;
        int ii = pair >> 1, sub = pair & 1;
        int col = 2 * (cg2 + 8 * ii) + sub;
        atomicAdd(&g_S[b * 320 + col * 4 + stat], sum);
    }
}

// ---------------- tail: 2 keypoints per block (80 blocks = 1 wave) ----------------
__global__ void __launch_bounds__(256) k_tail(const float* __restrict__ x_rec,
                                              const float* __restrict__ h_rec,
                                              const float* __restrict__ W_mlp,
                                              const float* __restrict__ b_mlp,
                                              const float* __restrict__ gamma,
                                              const float* __restrict__ beta,
                                              float* __restrict__ out) {
    __shared__ float sd[256 * KNN];
    __shared__ int   si[256 * KNN];
    __shared__ float kpos[2][3];
    __shared__ float hm[2][FF];
    __shared__ float dk8[2][KNN];
    __shared__ int   id8[2][KNN];
    __shared__ float rbuf[32];
    __shared__ float mv[2][2];
    int bk0 = blockIdx.x * 2;
    int b = bk0 / NK;
    int tid = threadIdx.x;

    if (tid < 2) {
        int bk = bk0 + tid;
        float p0 = 0.f, p1 = 0.f, p2 = 0.f;
#pragma unroll
        for (int h = 0; h < HH; h++) {
            const float* S = g_S + bk * 16 + h * 4;
            float inv = 1.f / S[0];
            p0 += S[1] * inv; p1 += S[2] * inv; p2 += S[3] * inv;
        }
        p0 *= 0.25f; p1 *= 0.25f; p2 *= 0.25f;
        kpos[tid][0] = p0; kpos[tid][1] = p1; kpos[tid][2] = p2;
        out[bk * 3 + 0] = p0; out[bk * 3 + 1] = p1; out[bk * 3 + 2] = p2;
    }
    __syncthreads();
    float px0 = kpos[0][0], py0 = kpos[0][1], pz0 = kpos[0][2];
    float px1 = kpos[1][0], py1 = kpos[1][1], pz1 = kpos[1][2];

    // shared distance scan: one pass over x_rec feeds both top-8s
    float bd0[KNN], bd1[KNN]; int bi0[KNN], bi1[KNN];
#pragma unroll
    for (int j = 0; j < KNN; j++) {
        bd0[j] = 3.4e38f; bi0[j] = 0x7fffffff;
        bd1[j] = 3.4e38f; bi1[j] = 0x7fffffff;
    }
    const float* xb = x_rec + (size_t)b * NR * 3;
#pragma unroll 1
    for (int base = 0; base < NR; base += 1024) {
        float xx[4], yy[4], zz[4];
#pragma unroll
        for (int u = 0; u < 4; u++) {
            int r = base + u * 256 + tid;
            xx[u] = xb[r * 3 + 0];
            yy[u] = xb[r * 3 + 1];
            zz[u] = xb[r * 3 + 2];
        }
#pragma unroll
        for (int u = 0; u < 4; u++) {
            int r = base + u * 256 + tid;
            float dx0 = xx[u] - px0, dy0 = yy[u] - py0, dz0 = zz[u] - pz0;
            float d20 = dx0 * dx0 + dy0 * dy0 + dz0 * dz0;
            float dx1 = xx[u] - px1, dy1 = yy[u] - py1, dz1 = zz[u] - pz1;
            float d21 = dx1 * dx1 + dy1 * dy1 + dz1 * dz1;
            if (d20 < bd0[KNN - 1]) {
                int p = KNN - 1;
                while (p > 0 && d20 < bd0[p - 1]) { bd0[p] = bd0[p - 1]; bi0[p] = bi0[p - 1]; p--; }
                bd0[p] = d20; bi0[p] = r;
            }
            if (d21 < bd1[KNN - 1]) {
                int p = KNN - 1;
                while (p > 0 && d21 < bd1[p - 1]) { bd1[p] = bd1[p - 1]; bi1[p] = bi1[p - 1]; p--; }
                bd1[p] = d21; bi1[p] = r;
            }
        }
    }

    // two sequential merge trees over shared smem
#pragma unroll 1
    for (int kk = 0; kk < 2; kk++) {
        __syncthreads();   // protect sd/si reuse
#pragma unroll
        for (int j = 0; j < KNN; j++) {
            sd[tid * KNN + j] = kk ? bd1[j] : bd0[j];
            si[tid * KNN + j] = kk ? bi1[j] : bi0[j];
        }
        for (int stride = 128; stride >= 1; stride >>= 1) {
            __syncthreads();
            if (tid < stride) {
                float od[KNN]; int oi[KNN];
                int ia = 0, ib = 0;
#pragma unroll
                for (int o = 0; o < KNN; o++) {
                    float da = sd[tid * KNN + ia], db = sd[(tid + stride) * KNN + ib];
                    int xa = si[tid * KNN + ia], xb2 = si[(tid + stride) * KNN + ib];
                    bool ta = (da < db) || (da == db && xa < xb2);
                    if (ta) { od[o] = da; oi[o] = xa; ia++; }
                    else    { od[o] = db; oi[o] = xb2; ib++; }
                }
#pragma unroll
                for (int o = 0; o < KNN; o++) { sd[tid * KNN + o] = od[o]; si[tid * KNN + o] = oi[o]; }
            }
        }
        __syncthreads();
        if (tid < KNN) { dk8[kk][tid] = sqrtf(sd[tid]); id8[kk][tid] = si[tid]; }
    }
    __syncthreads();

    // gather kNN means for both keypoints
    int j = tid;
    float a0 = 0.f, a1 = 0.f;
#pragma unroll
    for (int t = 0; t < KNN; t++) {
        a0 += h_rec[((size_t)b * NR + id8[0][t]) * FF + j];
        a1 += h_rec[((size_t)b * NR + id8[1][t]) * FF + j];
    }
    hm[0][j] = a0 * 0.125f;
    hm[1][j] = a1 * 0.125f;
    __syncthreads();

    // MLP: share each W load between the two keypoints; split chains
    float y0a = b_mlp[j], y0b = 0.f, y1a = y0a, y1b = 0.f;
#pragma unroll 8
    for (int i = 0; i < FF; i += 2) {
        float w0 = W_mlp[i * FF + j];
        float w1 = W_mlp[(i + 1) * FF + j];
        y0a += hm[0][i] * w0;     y0b += hm[0][i + 1] * w1;
        y1a += hm[1][i] * w0;     y1b += hm[1][i + 1] * w1;
    }
#pragma unroll
    for (int t = 0; t < KNN; t++) {
        float w = W_mlp[(FF + t) * FF + j];
        y0a += dk8[0][t] * w;
        y1a += dk8[1][t] * w;
    }
    float y0 = y0a + y0b;
    float y1 = y1a + y1b;
    y0 = y0 / (1.f + expf(-y0));
    y1 = y1 / (1.f + expf(-y1));

    // LayerNorm for both (parallel reductions)
    float s10 = y0, s20 = y0 * y0, s11 = y1, s21 = y1 * y1;
#pragma unroll
    for (int d = 16; d; d >>= 1) {
        s10 += __shfl_down_sync(0xffffffffu, s10, d);
        s20 += __shfl_down_sync(0xffffffffu, s20, d);
        s11 += __shfl_down_sync(0xffffffffu, s11, d);
        s21 += __shfl_down_sync(0xffffffffu, s21, d);
    }
    int lane = j & 31, w = j >> 5;
    if (lane == 0) {
        rbuf[w] = s10; rbuf[8 + w] = s20; rbuf[16 + w] = s11; rbuf[24 + w] = s21;
    }
    __syncthreads();
    if (tid < 2) {
        float sa = 0.f, sb = 0.f;
#pragma unroll
        for (int w2 = 0; w2 < 8; w2++) { sa += rbuf[tid * 16 + w2]; sb += rbuf[tid * 16 + 8 + w2]; }
        float mu = sa * (1.f / 256.f);
        mv[tid][0] = mu;
        mv[tid][1] = sb * (1.f / 256.f) - mu * mu;
    }
    __syncthreads();
    float g = gamma[j], be = beta[j];
    {
        float inv = rsqrtf(mv[0][1] + 1e-5f);
        out[BB * NK * 3 + bk0 * FF + j] = (y0 - mv[0][0]) * inv * g + be;
    }
    {
        float inv = rsqrtf(mv[1][1] + 1e-5f);
        out[BB * NK * 3 + (bk0 + 1) * FF + j] = (y1 - mv[1][0]) * inv * g + be;
    }
}

// ---------------- launch ----------------
extern "C" void kernel_launch(void* const* d_in, const int* in_sizes, int n_in,
                              void* d_out, int out_size) {
    const float* h_rec = (const float*)d_in[0];
    const float* x_rec = (const float*)d_in[1];
    const float* h0_kp = (const float*)d_in[2];
    const float* W_src = (const float*)d_in[3];
    const float* W_mlp = (const float*)d_in[4];
    const float* b_mlp = (const float*)d_in[5];
    const float* gamma = (const float*)d_in[6];
    const float* beta  = (const float*)d_in[7];
    float* out = (float*)d_out;

    const int attn_smem = ATTN_SMEM_FLOATS * 4;
    const int v_smem = V_SMEM_FLOATS * 4;
    const int ft_smem = FT_SMEM_FLOATS * 4;
    cudaFuncSetAttribute(k_attn, cudaFuncAttributeMaxDynamicSharedMemorySize, attn_smem);
    cudaFuncSetAttribute(k_V, cudaFuncAttributeMaxDynamicSharedMemorySize, v_smem);
    cudaFuncSetAttribute(k_ftdst, cudaFuncAttributeMaxDynamicSharedMemorySize, ft_smem);

    k_ftdst<<<dim3(16, BB), 256, ft_smem>>>(h0_kp, W_src);      // launch 1
    k_V<<<dim3(16, BB), 256, v_smem>>>(W_src);                  // launch 2
    k_zeroS<<<(BB * NK * HH * 4 + 255) / 256, 256>>>();         // launch 3
    k_attn<<<dim3(32, BB), 256, attn_smem>>>(h_rec, x_rec);     // launch 4 -> profiled
    k_tail<<<BB * NK / 2, 256>>>(x_rec, h_rec, W_mlp, b_mlp, gamma, beta, out);
}

// round 6
// speedup vs baseline: 1.2268x; 1.2268x over previous
#include <cuda_runtime.h>
#include <cuda_bf16.h>
#include <cstdint>

// ---------------- problem constants ----------------
#define BB   8
#define NR   4096
#define NK   20
#define FF   256
#define HH   4
#define KH   80
#define KNN  8

// ---------------- device scratch ----------------
__device__ float g_ftdst[BB * NK * 1024];
__device__ float g_V[BB * FF * KH];
__device__ float g_S[BB * NK * HH * 4];

// ---------------- helpers ----------------
__device__ __forceinline__ unsigned long long pack2(float x, float y) {
    unsigned long long r;
    asm("mov.b64 %0, {%1, %2};" : "=l"(r) : "f"(x), "f"(y));
    return r;
}
__device__ __forceinline__ void unpack2(unsigned long long v, float& x, float& y) {
    asm("mov.b64 {%0, %1}, %2;" : "=f"(x), "=f"(y) : "l"(v));
}
__device__ __forceinline__ void fma2(unsigned long long& d, unsigned long long a, unsigned long long b) {
    asm("fma.rn.f32x2 %0, %1, %2, %0;" : "+l"(d) : "l"(a), "l"(b));
}
__device__ __forceinline__ void cp_async16(uint32_t dst, const void* src) {
    asm volatile("cp.async.ca.shared.global [%0], [%1], 16;" :: "r"(dst), "l"(src));
}
__device__ __forceinline__ void cp_commit() { asm volatile("cp.async.commit_group;"); }

// ---------------- A1: ft_dst = h0_kp @ W_src ----------------
#define FT_SMEM_FLOATS (NK * FF + 256 * 65)
__global__ void __launch_bounds__(256) k_ftdst(const float* __restrict__ h0,
                                               const float* __restrict__ W) {
    extern __shared__ float sm[];
    float* hs = sm;
    float* ws = sm + NK * FF;
    int b = blockIdx.y, ct = blockIdx.x;
    if (ct == 0) {
        for (int i = threadIdx.x; i < FF * KH; i += 256) g_V[b * FF * KH + i] = 0.f;
    }
    for (int i = threadIdx.x; i < NK * FF; i += 256) hs[i] = h0[b * NK * FF + i];
#pragma unroll 8
    for (int i = threadIdx.x; i < 256 * 64; i += 256) {
        int f = i >> 6, c = i & 63;
        ws[f * 65 + c] = W[f * 1024 + ct * 64 + c];
    }
    __syncthreads();
    int cg = threadIdx.x & 63;
    int rgp = threadIdx.x >> 6;
    float acc[5] = {0.f, 0.f, 0.f, 0.f, 0.f};
#pragma unroll 8
    for (int f = 0; f < 256; f++) {
        float w = ws[f * 65 + cg];
#pragma unroll
        for (int q = 0; q < 5; q++) acc[q] += hs[(rgp * 5 + q) * 256 + f] * w;
    }
    int c = ct * 64 + cg;
#pragma unroll
    for (int q = 0; q < 5; q++)
        g_ftdst[(b * NK + rgp * 5 + q) * 1024 + c] = acc[q];
}

// ---------------- A2: V reduction ----------------
#define V_SMEM_FLOATS (64 * 257 + NK * 256)
__global__ void __launch_bounds__(256) k_V(const float* __restrict__ W) {
    extern __shared__ float sm[];
    float* ws2 = sm;
    float* fts2 = sm + 64 * 257;
    int b = blockIdx.y;
    int ft = blockIdx.x >> 2, ds = blockIdx.x & 3;
    int fbase = ft * 64, dbase = ds * 64;
#pragma unroll 4
    for (int i = threadIdx.x; i < 64 * 256; i += 256) {
        int fi = i >> 8, rest = i & 255;
        int h = rest >> 6, dd = rest & 63;
        ws2[fi * 257 + rest] = W[(fbase + fi) * 1024 + h * 256 + dbase + dd];
    }
#pragma unroll 4
    for (int i = threadIdx.x; i < NK * 256; i += 256) {
        int rest = i & 255;
        int h = rest >> 6, dd = rest & 63;
        int k = i >> 8;
        fts2[i] = g_ftdst[b * 20480 + k * 1024 + h * 256 + dbase + dd];
    }
    __syncthreads();
    int fi = threadIdx.x & 63;
    int h  = threadIdx.x >> 6;
    float acc[NK];
#pragma unroll
    for (int j = 0; j < NK; j++) acc[j] = 0.f;
    const float* wp = ws2 + fi * 257 + h * 64;
    const float* fp = fts2 + h * 64;
#pragma unroll 2
    for (int dd = 0; dd < 64; dd++) {
        float w = wp[dd];
#pragma unroll
        for (int j = 0; j < NK; j++) acc[j] += w * fp[j * 256 + dd];
    }
    float* gv = g_V + b * (FF * KH) + (fbase + fi) * KH + h;
#pragma unroll
    for (int j = 0; j < NK; j++)
        atomicAdd(gv + j * 4, acc[j] * 0.0625f);
}

// ---------------- zero g_S ----------------
__global__ void k_zeroS() {
    int i = blockIdx.x * blockDim.x + threadIdx.x;
    if (i < BB * NK * HH * 4) g_S[i] = 0.f;
}

// ---------------- B: fused  a = h_rec @ V ; exp ; 4 moments ----------------
// grid (16, 8) = 128 blocks (1 wave, 1 CTA/SM), 256 threads, 256 rows/CTA.
// h staged via cp.async double-buffered f-chunks of 32; thread: 8 rows x 5 col-pairs.
#define ATTN_VS   (256 * 96)         // 24576 floats (permuted V)
#define ATTN_HS   (2 * 256 * 32)     // 16384 floats (double-buffered h chunks)
#define ATTN_RED  2560
#define ATTN_SMEM_FLOATS (ATTN_VS + ATTN_HS + ATTN_RED)
__global__ void __launch_bounds__(256, 1) k_attn(const float* __restrict__ h_rec,
                                                 const float* __restrict__ x_rec) {
    extern __shared__ float sm[];
    float* Vsp = sm;
    float* hs  = sm + ATTN_VS;
    float* red = sm + ATTN_VS + ATTN_HS;
    int b = blockIdx.y;
    int tid = threadIdx.x;
    int lane = tid & 31, w = tid >> 5;
    int rg = tid >> 3, cg = tid & 7;
    uint32_t hs_u32 = (uint32_t)__cvta_generic_to_shared(hs);

    int rowbase = blockIdx.x * 256;
    const float* hblk = h_rec + ((size_t)b * NR + rowbase) * FF;

    // issue chunk 0 loads first (overlap with V permute)
    {
        const float* src0 = hblk;
#pragma unroll
        for (int q = 0; q < 8; q++) {
            int s = tid + q * 256;
            int row = s >> 3, f16 = s & 7;
            const float* src = src0 + (size_t)row * FF + f16 * 4;
            uint32_t dst = hs_u32 + (uint32_t)(row * 32 + (((f16 + (row >> 3)) & 7) << 2)) * 4u;
            cp_async16(dst, src);
        }
        cp_commit();
    }

    // load + permute V: thread's 10 columns contiguous (padded to 12)
    const float* gV = g_V + b * (FF * KH);
    for (int t = tid; t < FF * KH; t += 256) {
        int f = t / 80, q = t % 80;
        int c2 = q / 10, j = q % 10;
        int ip = j >> 1, sub = j & 1;
        int c = ((c2 + 8 * ip) << 1) | sub;
        Vsp[f * 96 + c2 * 12 + j] = gV[f * 80 + c];
    }
    for (int t = tid; t < ATTN_RED; t += 256) red[t] = 0.f;

    int row0 = rg * 8;                       // 8 rows per thread (block-local)
    unsigned long long acc[8][5];
#pragma unroll
    for (int r = 0; r < 8; r++)
#pragma unroll
        for (int i = 0; i < 5; i++) acc[r][i] = 0ull;

    const char* vb0 = (const char*)(Vsp + cg * 12);

#pragma unroll 1
    for (int c = 0; c < 8; c++) {            // 8 f-chunks of 32
        if (c < 7) {                          // issue chunk c+1
            int buf = (c + 1) & 1;
            const float* src0 = hblk + (c + 1) * 32;
#pragma unroll
            for (int q = 0; q < 8; q++) {
                int s = tid + q * 256;
                int row = s >> 3, f16 = s & 7;
                const float* src = src0 + (size_t)row * FF + f16 * 4;
                uint32_t dst = hs_u32 + (uint32_t)(buf * 8192 + row * 32 +
                                   (((f16 + (row >> 3)) & 7) << 2)) * 4u;
                cp_async16(dst, src);
            }
            cp_commit();
            asm volatile("cp.async.wait_group 1;");
        } else {
            asm volatile("cp.async.wait_group 0;");
        }
        __syncthreads();

        const float* hsb = hs + (c & 1) * 8192 + row0 * 32;
        const char* vbase = vb0 + (size_t)(c * 32) * 384;
#pragma unroll 2
        for (int k = 0; k < 8; k++) {         // 8 float4 per chunk
            float4 a[8];
            int swz = ((k + rg) & 7) << 2;
#pragma unroll
            for (int r = 0; r < 8; r++)
                a[r] = *(const float4*)(hsb + r * 32 + swz);
#pragma unroll
            for (int e = 0; e < 4; e++) {
                const ulonglong2* vp = (const ulonglong2*)(vbase + (size_t)(k * 4 + e) * 384);
                ulonglong2 v01 = vp[0];
                ulonglong2 v23 = vp[1];
                unsigned long long v4 = *(const unsigned long long*)(vp + 2);
#pragma unroll
                for (int r = 0; r < 8; r++) {
                    float h = (e == 0) ? a[r].x : (e == 1) ? a[r].y : (e == 2) ? a[r].z : a[r].w;
                    unsigned long long H = pack2(h, h);
                    fma2(acc[r][0], H, v01.x);
                    fma2(acc[r][1], H, v01.y);
                    fma2(acc[r][2], H, v23.x);
                    fma2(acc[r][3], H, v23.y);
                    fma2(acc[r][4], H, v4);
                }
            }
        }
        __syncthreads();                       // buffer reuse safety
    }

    // epilogue: exp + 4 moments over this thread's 8 rows
    const float* xp = x_rec + ((size_t)b * NR + rowbase + row0) * 3;
    float xr[8][3];
#pragma unroll
    for (int r = 0; r < 8; r++) {
        xr[r][0] = xp[r * 3 + 0];
        xr[r][1] = xp[r * 3 + 1];
        xr[r][2] = xp[r * 3 + 2];
    }
#pragma unroll
    for (int i = 0; i < 5; i++) {
        float al[8], ah[8];
#pragma unroll
        for (int r = 0; r < 8; r++) unpack2(acc[r][i], al[r], ah[r]);
#pragma unroll
        for (int sub = 0; sub < 2; sub++) {
            float v0 = 0.f, v1 = 0.f, v2 = 0.f, v3 = 0.f;
#pragma unroll
            for (int r = 0; r < 8; r++) {
                float e = expf(sub ? ah[r] : al[r]);
                v0 += e;
                v1 += e * xr[r][0];
                v2 += e * xr[r][1];
                v3 += e * xr[r][2];
            }
#pragma unroll
            for (int d = 16; d >= 8; d >>= 1) {
                v0 += __shfl_down_sync(0xffffffffu, v0, d);
                v1 += __shfl_down_sync(0xffffffffu, v1, d);
                v2 += __shfl_down_sync(0xffffffffu, v2, d);
                v3 += __shfl_down_sync(0xffffffffu, v3, d);
            }
            if (lane < 8) {
                float* rp = red + w * 320 + cg * 40 + (2 * i + sub) * 4;
                rp[0] += v0; rp[1] += v1; rp[2] += v2; rp[3] += v3;
            }
        }
    }
    __syncthreads();
    for (int v = tid; v < 320; v += 256) {
        int cg2 = v / 40, sidx = v % 40;
        float sum = 0.f;
#pragma unroll
        for (int w2 = 0; w2 < 8; w2++) sum += red[w2 * 320 + cg2 * 40 + sidx];
        int pair = sidx >> 2, stat = sidx & 3;
        int ii = pair >> 1, sub = pair & 1;
        int col = 2 * (cg2 + 8 * ii) + sub;
        atomicAdd(&g_S[b * 320 + col * 4 + stat], sum);
    }
}

// ---------------- tail (R4 version, reverted): kp_pos + top-8 + MLP + LN ----------------
__global__ void __launch_bounds__(256) k_tail(const float* __restrict__ x_rec,
                                              const float* __restrict__ h_rec,
                                              const float* __restrict__ W_mlp,
                                              const float* __restrict__ b_mlp,
                                              const float* __restrict__ gamma,
                                              const float* __restrict__ beta,
                                              float* __restrict__ out) {
    __shared__ float sd[256 * KNN];
    __shared__ int   si[256 * KNN];
    __shared__ float kpos[3];
    __shared__ float hm[FF];
    __shared__ float dk8[KNN];
    __shared__ int   id8[KNN];
    __shared__ float rbuf[16];
    __shared__ float mv[2];
    int bk = blockIdx.x, b = bk / NK, tid = threadIdx.x;

    if (tid == 0) {
        float p0 = 0.f, p1 = 0.f, p2 = 0.f;
#pragma unroll
        for (int h = 0; h < HH; h++) {
            const float* S = g_S + bk * 16 + h * 4;
            float inv = 1.f / S[0];
            p0 += S[1] * inv; p1 += S[2] * inv; p2 += S[3] * inv;
        }
        p0 *= 0.25f; p1 *= 0.25f; p2 *= 0.25f;
        kpos[0] = p0; kpos[1] = p1; kpos[2] = p2;
        out[bk * 3 + 0] = p0; out[bk * 3 + 1] = p1; out[bk * 3 + 2] = p2;
    }
    __syncthreads();
    float px = kpos[0], py = kpos[1], pz = kpos[2];

    float bd[KNN]; int bi[KNN];
#pragma unroll
    for (int j = 0; j < KNN; j++) { bd[j] = 3.4e38f; bi[j] = 0x7fffffff; }
    const float* xb = x_rec + (size_t)b * NR * 3;
#pragma unroll 1
    for (int base = 0; base < NR; base += 1024) {
        float d2v[4];
#pragma unroll
        for (int u = 0; u < 4; u++) {
            int r = base + u * 256 + tid;
            float dx = xb[r * 3 + 0] - px;
            float dy = xb[r * 3 + 1] - py;
            float dz = xb[r * 3 + 2] - pz;
            d2v[u] = dx * dx + dy * dy + dz * dz;
        }
#pragma unroll
        for (int u = 0; u < 4; u++) {
            float d2 = d2v[u];
            if (d2 < bd[KNN - 1]) {
                int r = base + u * 256 + tid;
                int p = KNN - 1;
                while (p > 0 && d2 < bd[p - 1]) { bd[p] = bd[p - 1]; bi[p] = bi[p - 1]; p--; }
                bd[p] = d2; bi[p] = r;
            }
        }
    }
#pragma unroll
    for (int j = 0; j < KNN; j++) { sd[tid * KNN + j] = bd[j]; si[tid * KNN + j] = bi[j]; }
    for (int stride = 128; stride >= 1; stride >>= 1) {
        __syncthreads();
        if (tid < stride) {
            float od[KNN]; int oi[KNN];
            int ia = 0, ib = 0;
#pragma unroll
            for (int o = 0; o < KNN; o++) {
                float da = sd[tid * KNN + ia], db = sd[(tid + stride) * KNN + ib];
                int xa = si[tid * KNN + ia], xb2 = si[(tid + stride) * KNN + ib];
                bool ta = (da < db) || (da == db && xa < xb2);
                if (ta) { od[o] = da; oi[o] = xa; ia++; }
                else    { od[o] = db; oi[o] = xb2; ib++; }
            }
#pragma unroll
            for (int o = 0; o < KNN; o++) { sd[tid * KNN + o] = od[o]; si[tid * KNN + o] = oi[o]; }
        }
    }
    __syncthreads();
    if (tid < KNN) { dk8[tid] = sqrtf(sd[tid]); id8[tid] = si[tid]; }
    __syncthreads();

    int j = tid;
    float a = 0.f;
#pragma unroll
    for (int t = 0; t < KNN; t++)
        a += h_rec[((size_t)b * NR + id8[t]) * FF + j];
    hm[j] = a * 0.125f;
    __syncthreads();

    float y = b_mlp[j];
#pragma unroll 16
    for (int i = 0; i < FF; i++) y += hm[i] * W_mlp[i * FF + j];
#pragma unroll
    for (int t = 0; t < KNN; t++) y += dk8[t] * W_mlp[(FF + t) * FF + j];
    y = y / (1.f + expf(-y));

    float s1 = y, s2 = y * y;
#pragma unroll
    for (int d = 16; d; d >>= 1) {
        s1 += __shfl_down_sync(0xffffffffu, s1, d);
        s2 += __shfl_down_sync(0xffffffffu, s2, d);
    }
    int lane = j & 31, w = j >> 5;
    if (lane == 0) { rbuf[w] = s1; rbuf[8 + w] = s2; }
    __syncthreads();
    if (j == 0) {
        float sa = 0.f, sb = 0.f;
#pragma unroll
        for (int w2 = 0; w2 < 8; w2++) { sa += rbuf[w2]; sb += rbuf[8 + w2]; }
        float mu = sa * (1.f / 256.f);
        mv[0] = mu;
        mv[1] = sb * (1.f / 256.f) - mu * mu;
    }
    __syncthreads();
    float mu = mv[0];
    float inv = rsqrtf(mv[1] + 1e-5f);
    out[BB * NK * 3 + bk * FF + j] = (y - mu) * inv * gamma[j] + beta[j];
}

// ---------------- launch ----------------
extern "C" void kernel_launch(void* const* d_in, const int* in_sizes, int n_in,
                              void* d_out, int out_size) {
    const float* h_rec = (const float*)d_in[0];
    const float* x_rec = (const float*)d_in[1];
    const float* h0_kp = (const float*)d_in[2];
    const float* W_src = (const float*)d_in[3];
    const float* W_mlp = (const float*)d_in[4];
    const float* b_mlp = (const float*)d_in[5];
    const float* gamma = (const float*)d_in[6];
    const float* beta  = (const float*)d_in[7];
    float* out = (float*)d_out;

    const int attn_smem = ATTN_SMEM_FLOATS * 4;
    const int v_smem = V_SMEM_FLOATS * 4;
    const int ft_smem = FT_SMEM_FLOATS * 4;
    cudaFuncSetAttribute(k_attn, cudaFuncAttributeMaxDynamicSharedMemorySize, attn_smem);
    cudaFuncSetAttribute(k_V, cudaFuncAttributeMaxDynamicSharedMemorySize, v_smem);
    cudaFuncSetAttribute(k_ftdst, cudaFuncAttributeMaxDynamicSharedMemorySize, ft_smem);

    k_ftdst<<<dim3(16, BB), 256, ft_smem>>>(h0_kp, W_src);      // launch 1
    k_V<<<dim3(16, BB), 256, v_smem>>>(W_src);                  // launch 2
    k_zeroS<<<(BB * NK * HH * 4 + 255) / 256, 256>>>();         // launch 3
    k_attn<<<dim3(16, BB), 256, attn_smem>>>(h_rec, x_rec);     // launch 4 -> profiled
    k_tail<<<BB * NK, 256>>>(x_rec, h_rec, W_mlp, b_mlp, gamma, beta, out);
}

// round 7
// speedup vs baseline: 1.3012x; 1.0606x over previous
#include <cuda_runtime.h>
#include <cuda_bf16.h>
#include <cstdint>

// ---------------- problem constants ----------------
#define BB   8
#define NR   4096
#define NK   20
#define FF   256
#define HH   4
#define KH   80
#define KNN  8

// ---------------- device scratch ----------------
__device__ float g_ftdst[BB * NK * 1024];
__device__ float g_V[BB * FF * KH];
__device__ float g_S[BB * NK * HH * 4];

// ---------------- helpers ----------------
__device__ __forceinline__ unsigned long long pack2(float x, float y) {
    unsigned long long r;
    asm("mov.b64 %0, {%1, %2};" : "=l"(r) : "f"(x), "f"(y));
    return r;
}
__device__ __forceinline__ void unpack2(unsigned long long v, float& x, float& y) {
    asm("mov.b64 {%0, %1}, %2;" : "=f"(x), "=f"(y) : "l"(v));
}
__device__ __forceinline__ void fma2(unsigned long long& d, unsigned long long a, unsigned long long b) {
    asm("fma.rn.f32x2 %0, %1, %2, %0;" : "+l"(d) : "l"(a), "l"(b));
}
__device__ __forceinline__ void cp_async16(uint32_t dst, const void* src) {
    asm volatile("cp.async.ca.shared.global [%0], [%1], 16;" :: "r"(dst), "l"(src));
}
__device__ __forceinline__ void cp_commit() { asm volatile("cp.async.commit_group;"); }

// ---------------- A1: ft_dst = h0_kp @ W_src (+ zero g_V, g_S) ----------------
#define FT_SMEM_FLOATS (NK * FF + 256 * 65)
__global__ void __launch_bounds__(256) k_ftdst(const float* __restrict__ h0,
                                               const float* __restrict__ W) {
    extern __shared__ float sm[];
    float* hs = sm;
    float* ws = sm + NK * FF;
    int b = blockIdx.y, ct = blockIdx.x;
    if (ct == 0) {
        for (int i = threadIdx.x; i < FF * KH; i += 256) g_V[b * FF * KH + i] = 0.f;
        for (int i = threadIdx.x; i < NK * HH * 4; i += 256) g_S[b * NK * HH * 4 + i] = 0.f;
    }
    for (int i = threadIdx.x; i < NK * FF; i += 256) hs[i] = h0[b * NK * FF + i];
#pragma unroll 8
    for (int i = threadIdx.x; i < 256 * 64; i += 256) {
        int f = i >> 6, c = i & 63;
        ws[f * 65 + c] = W[f * 1024 + ct * 64 + c];
    }
    __syncthreads();
    int cg = threadIdx.x & 63;
    int rgp = threadIdx.x >> 6;
    float acc[5] = {0.f, 0.f, 0.f, 0.f, 0.f};
#pragma unroll 8
    for (int f = 0; f < 256; f++) {
        float w = ws[f * 65 + cg];
#pragma unroll
        for (int q = 0; q < 5; q++) acc[q] += hs[(rgp * 5 + q) * 256 + f] * w;
    }
    int c = ct * 64 + cg;
#pragma unroll
    for (int q = 0; q < 5; q++)
        g_ftdst[(b * NK + rgp * 5 + q) * 1024 + c] = acc[q];
}

// ---------------- A2: V reduction ----------------
#define V_SMEM_FLOATS (64 * 257 + NK * 256)
__global__ void __launch_bounds__(256) k_V(const float* __restrict__ W) {
    extern __shared__ float sm[];
    float* ws2 = sm;
    float* fts2 = sm + 64 * 257;
    int b = blockIdx.y;
    int ft = blockIdx.x >> 2, ds = blockIdx.x & 3;
    int fbase = ft * 64, dbase = ds * 64;
#pragma unroll 4
    for (int i = threadIdx.x; i < 64 * 256; i += 256) {
        int fi = i >> 8, rest = i & 255;
        int h = rest >> 6, dd = rest & 63;
        ws2[fi * 257 + rest] = W[(fbase + fi) * 1024 + h * 256 + dbase + dd];
    }
#pragma unroll 4
    for (int i = threadIdx.x; i < NK * 256; i += 256) {
        int rest = i & 255;
        int h = rest >> 6, dd = rest & 63;
        int k = i >> 8;
        fts2[i] = g_ftdst[b * 20480 + k * 1024 + h * 256 + dbase + dd];
    }
    __syncthreads();
    int fi = threadIdx.x & 63;
    int h  = threadIdx.x >> 6;
    float acc[NK];
#pragma unroll
    for (int j = 0; j < NK; j++) acc[j] = 0.f;
    const float* wp = ws2 + fi * 257 + h * 64;
    const float* fp = fts2 + h * 64;
#pragma unroll 2
    for (int dd = 0; dd < 64; dd++) {
        float w = wp[dd];
#pragma unroll
        for (int j = 0; j < NK; j++) acc[j] += w * fp[j * 256 + dd];
    }
    float* gv = g_V + b * (FF * KH) + (fbase + fi) * KH + h;
#pragma unroll
    for (int j = 0; j < NK; j++)
        atomicAdd(gv + j * 4, acc[j] * 0.0625f);
}

// ---------------- B: fused  a = h_rec @ V ; exp ; 4 moments ----------------
// grid (16, 8) = 128 blocks (1 wave, 1 CTA/SM), 512 threads, 256 rows/CTA.
// Thread tile: 4 rows x 5 column-pairs. h staged via cp.async double-buffered
// f-chunks of 32 (swizzled, conflict-free). 4 warps/SMSP fill issue slots.
#define ATTN_VS   (256 * 96)         // 24576 floats (permuted V)
#define ATTN_HS   (2 * 256 * 32)     // 16384 floats (double-buffered h chunks)
#define ATTN_RED  (16 * 320)         // 5120
#define ATTN_SMEM_FLOATS (ATTN_VS + ATTN_HS + ATTN_RED)
__global__ void __launch_bounds__(512, 1) k_attn(const float* __restrict__ h_rec,
                                                 const float* __restrict__ x_rec) {
    extern __shared__ float sm[];
    float* Vsp = sm;
    float* hs  = sm + ATTN_VS;
    float* red = sm + ATTN_VS + ATTN_HS;
    int b = blockIdx.y;
    int tid = threadIdx.x;
    int lane = tid & 31, w = tid >> 5;
    int rg = tid >> 3, cg = tid & 7;      // rg 0..63, 4 rows each
    uint32_t hs_u32 = (uint32_t)__cvta_generic_to_shared(hs);

    int rowbase = blockIdx.x * 256;
    const float* hblk = h_rec + ((size_t)b * NR + rowbase) * FF;

    // issue chunk 0 loads (overlap with V permute)
    {
#pragma unroll
        for (int q = 0; q < 4; q++) {
            int s = tid + q * 512;
            int row = s >> 3, f16 = s & 7;
            const float* src = hblk + (size_t)row * FF + f16 * 4;
            uint32_t dst = hs_u32 + (uint32_t)(row * 32 + (((f16 + (row >> 2)) & 7) << 2)) * 4u;
            cp_async16(dst, src);
        }
        cp_commit();
    }

    // load + permute V: thread's 10 columns contiguous (padded to 12)
    const float* gV = g_V + b * (FF * KH);
    for (int t = tid; t < FF * KH; t += 512) {
        int f = t / 80, q = t % 80;
        int c2 = q / 10, j = q % 10;
        int ip = j >> 1, sub = j & 1;
        int c = ((c2 + 8 * ip) << 1) | sub;
        Vsp[f * 96 + c2 * 12 + j] = gV[f * 80 + c];
    }

    int row0 = rg * 4;                    // 4 rows per thread (block-local)
    unsigned long long acc[4][5];
#pragma unroll
    for (int r = 0; r < 4; r++)
#pragma unroll
        for (int i = 0; i < 5; i++) acc[r][i] = 0ull;

    const char* vb0 = (const char*)(Vsp + cg * 12);

#pragma unroll 1
    for (int c = 0; c < 8; c++) {          // 8 f-chunks of 32
        if (c < 7) {                        // issue chunk c+1
            int buf = (c + 1) & 1;
            const float* src0 = hblk + (c + 1) * 32;
#pragma unroll
            for (int q = 0; q < 4; q++) {
                int s = tid + q * 512;
                int row = s >> 3, f16 = s & 7;
                const float* src = src0 + (size_t)row * FF + f16 * 4;
                uint32_t dst = hs_u32 + (uint32_t)(buf * 8192 + row * 32 +
                                   (((f16 + (row >> 2)) & 7) << 2)) * 4u;
                cp_async16(dst, src);
            }
            cp_commit();
            asm volatile("cp.async.wait_group 1;");
        } else {
            asm volatile("cp.async.wait_group 0;");
        }
        __syncthreads();

        const float* hsb = hs + (c & 1) * 8192 + row0 * 32;
        const char* vbase = vb0 + (size_t)(c * 32) * 384;
#pragma unroll 2
        for (int k = 0; k < 8; k++) {       // 8 float4 per chunk
            float4 a[4];
            int swz = ((k + rg) & 7) << 2;
#pragma unroll
            for (int r = 0; r < 4; r++)
                a[r] = *(const float4*)(hsb + r * 32 + swz);
#pragma unroll
            for (int e = 0; e < 4; e++) {
                const ulonglong2* vp = (const ulonglong2*)(vbase + (size_t)(k * 4 + e) * 384);
                ulonglong2 v01 = vp[0];
                ulonglong2 v23 = vp[1];
                unsigned long long v4 = *(const unsigned long long*)(vp + 2);
#pragma unroll
                for (int r = 0; r < 4; r++) {
                    float h = (e == 0) ? a[r].x : (e == 1) ? a[r].y : (e == 2) ? a[r].z : a[r].w;
                    unsigned long long H = pack2(h, h);
                    fma2(acc[r][0], H, v01.x);
                    fma2(acc[r][1], H, v01.y);
                    fma2(acc[r][2], H, v23.x);
                    fma2(acc[r][3], H, v23.y);
                    fma2(acc[r][4], H, v4);
                }
            }
        }
        __syncthreads();                    // buffer reuse safety
    }

    // epilogue: exp + 4 moments over this thread's 4 rows
    const float* xp = x_rec + ((size_t)b * NR + rowbase + row0) * 3;
    float xr[4][3];
#pragma unroll
    for (int r = 0; r < 4; r++) {
        xr[r][0] = xp[r * 3 + 0];
        xr[r][1] = xp[r * 3 + 1];
        xr[r][2] = xp[r * 3 + 2];
    }
    // zero red (first touch after last barrier use of hs region is fine; red is distinct)
    for (int t = tid; t < ATTN_RED; t += 512) red[t] = 0.f;
    __syncthreads();
#pragma unroll
    for (int i = 0; i < 5; i++) {
        float al[4], ah[4];
#pragma unroll
        for (int r = 0; r < 4; r++) unpack2(acc[r][i], al[r], ah[r]);
#pragma unroll
        for (int sub = 0; sub < 2; sub++) {
            float v0 = 0.f, v1 = 0.f, v2 = 0.f, v3 = 0.f;
#pragma unroll
            for (int r = 0; r < 4; r++) {
                float e = expf(sub ? ah[r] : al[r]);
                v0 += e;
                v1 += e * xr[r][0];
                v2 += e * xr[r][1];
                v3 += e * xr[r][2];
            }
#pragma unroll
            for (int d = 16; d >= 8; d >>= 1) {
                v0 += __shfl_down_sync(0xffffffffu, v0, d);
                v1 += __shfl_down_sync(0xffffffffu, v1, d);
                v2 += __shfl_down_sync(0xffffffffu, v2, d);
                v3 += __shfl_down_sync(0xffffffffu, v3, d);
            }
            if (lane < 8) {
                float* rp = red + w * 320 + cg * 40 + (2 * i + sub) * 4;
                rp[0] += v0; rp[1] += v1; rp[2] += v2; rp[3] += v3;
            }
        }
    }
    __syncthreads();
    for (int v = tid; v < 320; v += 512) {
        int cg2 = v / 40, sidx = v % 40;
        float sum = 0.f;
#pragma unroll
        for (int w2 = 0; w2 < 16; w2++) sum += red[w2 * 320 + cg2 * 40 + sidx];
        int pair = sidx >> 2, stat = sidx & 3;
        int ii = pair >> 1, sub = pair & 1;
        int col = 2 * (cg2 + 8 * ii) + sub;
        atomicAdd(&g_S[b * 320 + col * 4 + stat], sum);
    }
}

// ---------------- tail: kp_pos + top-8 + gather/MLP/SiLU/LayerNorm ----------------
__global__ void __launch_bounds__(256) k_tail(const float* __restrict__ x_rec,
                                              const float* __restrict__ h_rec,
                                              const float* __restrict__ W_mlp,
                                              const float* __restrict__ b_mlp,
                                              const float* __restrict__ gamma,
                                              const float* __restrict__ beta,
                                              float* __restrict__ out) {
    __shared__ float sd[256 * KNN];
    __shared__ int   si[256 * KNN];
    __shared__ float kpos[3];
    __shared__ float hm[FF];
    __shared__ float dk8[KNN];
    __shared__ int   id8[KNN];
    __shared__ float rbuf[16];
    __shared__ float mv[2];
    int bk = blockIdx.x, b = bk / NK, tid = threadIdx.x;

    if (tid == 0) {
        float p0 = 0.f, p1 = 0.f, p2 = 0.f;
#pragma unroll
        for (int h = 0; h < HH; h++) {
            const float* S = g_S + bk * 16 + h * 4;
            float inv = 1.f / S[0];
            p0 += S[1] * inv; p1 += S[2] * inv; p2 += S[3] * inv;
        }
        p0 *= 0.25f; p1 *= 0.25f; p2 *= 0.25f;
        kpos[0] = p0; kpos[1] = p1; kpos[2] = p2;
        out[bk * 3 + 0] = p0; out[bk * 3 + 1] = p1; out[bk * 3 + 2] = p2;
    }
    __syncthreads();
    float px = kpos[0], py = kpos[1], pz = kpos[2];

    float bd[KNN]; int bi[KNN];
#pragma unroll
    for (int j = 0; j < KNN; j++) { bd[j] = 3.4e38f; bi[j] = 0x7fffffff; }
    const float* xb = x_rec + (size_t)b * NR * 3;
#pragma unroll 1
    for (int base = 0; base < NR; base += 1024) {
        float d2v[4];
#pragma unroll
        for (int u = 0; u < 4; u++) {
            int r = base + u * 256 + tid;
            float dx = xb[r * 3 + 0] - px;
            float dy = xb[r * 3 + 1] - py;
            float dz = xb[r * 3 + 2] - pz;
            d2v[u] = dx * dx + dy * dy + dz * dz;
        }
#pragma unroll
        for (int u = 0; u < 4; u++) {
            float d2 = d2v[u];
            if (d2 < bd[KNN - 1]) {
                int r = base + u * 256 + tid;
                int p = KNN - 1;
                while (p > 0 && d2 < bd[p - 1]) { bd[p] = bd[p - 1]; bi[p] = bi[p - 1]; p--; }
                bd[p] = d2; bi[p] = r;
            }
        }
    }
#pragma unroll
    for (int j = 0; j < KNN; j++) { sd[tid * KNN + j] = bd[j]; si[tid * KNN + j] = bi[j]; }
    for (int stride = 128; stride >= 1; stride >>= 1) {
        __syncthreads();
        if (tid < stride) {
            float od[KNN]; int oi[KNN];
            int ia = 0, ib = 0;
#pragma unroll
            for (int o = 0; o < KNN; o++) {
                float da = sd[tid * KNN + ia], db = sd[(tid + stride) * KNN + ib];
                int xa = si[tid * KNN + ia], xb2 = si[(tid + stride) * KNN + ib];
                bool ta = (da < db) || (da == db && xa < xb2);
                if (ta) { od[o] = da; oi[o] = xa; ia++; }
                else    { od[o] = db; oi[o] = xb2; ib++; }
            }
#pragma unroll
            for (int o = 0; o < KNN; o++) { sd[tid * KNN + o] = od[o]; si[tid * KNN + o] = oi[o]; }
        }
    }
    __syncthreads();
    if (tid < KNN) { dk8[tid] = sqrtf(sd[tid]); id8[tid] = si[tid]; }
    __syncthreads();

    int j = tid;
    float a = 0.f;
#pragma unroll
    for (int t = 0; t < KNN; t++)
        a += h_rec[((size_t)b * NR + id8[t]) * FF + j];
    hm[j] = a * 0.125f;
    __syncthreads();

    float y = b_mlp[j];
#pragma unroll 16
    for (int i = 0; i < FF; i++) y += hm[i] * W_mlp[i * FF + j];
#pragma unroll
    for (int t = 0; t < KNN; t++) y += dk8[t] * W_mlp[(FF + t) * FF + j];
    y = y / (1.f + expf(-y));

    float s1 = y, s2 = y * y;
#pragma unroll
    for (int d = 16; d; d >>= 1) {
        s1 += __shfl_down_sync(0xffffffffu, s1, d);
        s2 += __shfl_down_sync(0xffffffffu, s2, d);
    }
    int lane = j & 31, w = j >> 5;
    if (lane == 0) { rbuf[w] = s1; rbuf[8 + w] = s2; }
    __syncthreads();
    if (j == 0) {
        float sa = 0.f, sb = 0.f;
#pragma unroll
        for (int w2 = 0; w2 < 8; w2++) { sa += rbuf[w2]; sb += rbuf[8 + w2]; }
        float mu = sa * (1.f / 256.f);
        mv[0] = mu;
        mv[1] = sb * (1.f / 256.f) - mu * mu;
    }
    __syncthreads();
    float mu = mv[0];
    float inv = rsqrtf(mv[1] + 1e-5f);
    out[BB * NK * 3 + bk * FF + j] = (y - mu) * inv * gamma[j] + beta[j];
}

// ---------------- launch ----------------
extern "C" void kernel_launch(void* const* d_in, const int* in_sizes, int n_in,
                              void* d_out, int out_size) {
    const float* h_rec = (const float*)d_in[0];
    const float* x_rec = (const float*)d_in[1];
    const float* h0_kp = (const float*)d_in[2];
    const float* W_src = (const float*)d_in[3];
    const float* W_mlp = (const float*)d_in[4];
    const float* b_mlp = (const float*)d_in[5];
    const float* gamma = (const float*)d_in[6];
    const float* beta  = (const float*)d_in[7];
    float* out = (float*)d_out;

    const int attn_smem = ATTN_SMEM_FLOATS * 4;
    const int v_smem = V_SMEM_FLOATS * 4;
    const int ft_smem = FT_SMEM_FLOATS * 4;
    cudaFuncSetAttribute(k_attn, cudaFuncAttributeMaxDynamicSharedMemorySize, attn_smem);
    cudaFuncSetAttribute(k_V, cudaFuncAttributeMaxDynamicSharedMemorySize, v_smem);
    cudaFuncSetAttribute(k_ftdst, cudaFuncAttributeMaxDynamicSharedMemorySize, ft_smem);

    k_ftdst<<<dim3(16, BB), 256, ft_smem>>>(h0_kp, W_src);      // launch 1 (+zeroing)
    k_V<<<dim3(16, BB), 256, v_smem>>>(W_src);                  // launch 2
    k_attn<<<dim3(16, BB), 512, attn_smem>>>(h_rec, x_rec);     // launch 3
    k_tail<<<BB * NK, 256>>>(x_rec, h_rec, W_mlp, b_mlp, gamma, beta, out);  // launch 4 -> profiled
}

// round 9
// speedup vs baseline: 1.3661x; 1.0499x over previous
#include <cuda_runtime.h>
#include <cuda_bf16.h>
#include <cstdint>

// ---------------- problem constants ----------------
#define BB   8
#define NR   4096
#define NK   20
#define FF   256
#define HH   4
#define KH   80
#define KNN  8

// ---------------- device scratch ----------------
__device__ float g_ftdst[BB * NK * 1024];
__device__ float g_V[BB * FF * KH];
__device__ float g_S[BB * NK * HH * 4];
__device__ uint32_t g_Bfrag[BB * 20480];   // [b][split2][ks16][nt10][lane32][reg2]

// ---------------- helpers ----------------
__device__ __forceinline__ void cp_async16(uint32_t dst, const void* src) {
    asm volatile("cp.async.ca.shared.global [%0], [%1], 16;" :: "r"(dst), "l"(src));
}
// hi/lo bf16x2 split of float pair (f0 in low half)
__device__ __forceinline__ void split_pack(float f0, float f1, uint32_t& hi, uint32_t& lo) {
    uint32_t u0 = __float_as_uint(f0), u1 = __float_as_uint(f1);
    hi = (u1 & 0xFFFF0000u) | (u0 >> 16);
    float r0 = f0 - __uint_as_float(u0 & 0xFFFF0000u);
    float r1 = f1 - __uint_as_float(u1 & 0xFFFF0000u);
    asm("cvt.rn.bf16x2.f32 %0, %1, %2;" : "=r"(lo) : "f"(r1), "f"(r0));
}
__device__ __forceinline__ void mma16816(float* c, const uint32_t* a, uint32_t b0, uint32_t b1) {
    asm volatile(
        "mma.sync.aligned.m16n8k16.row.col.f32.bf16.bf16.f32 "
        "{%0,%1,%2,%3}, {%4,%5,%6,%7}, {%8,%9}, {%0,%1,%2,%3};"
        : "+f"(c[0]), "+f"(c[1]), "+f"(c[2]), "+f"(c[3])
        : "r"(a[0]), "r"(a[1]), "r"(a[2]), "r"(a[3]), "r"(b0), "r"(b1));
}

// ---------------- A1: ft_dst = h0_kp @ W_src (+ zero g_V) ----------------
#define FT_SMEM_FLOATS (NK * FF + 256 * 65)
__global__ void __launch_bounds__(256) k_ftdst(const float* __restrict__ h0,
                                               const float* __restrict__ W) {
    extern __shared__ float sm[];
    float* hs = sm;
    float* ws = sm + NK * FF;
    int b = blockIdx.y, ct = blockIdx.x;
    if (ct == 0) {
        for (int i = threadIdx.x; i < FF * KH; i += 256) g_V[b * FF * KH + i] = 0.f;
    }
    for (int i = threadIdx.x; i < NK * FF; i += 256) hs[i] = h0[b * NK * FF + i];
#pragma unroll 8
    for (int i = threadIdx.x; i < 256 * 64; i += 256) {
        int f = i >> 6, c = i & 63;
        ws[f * 65 + c] = W[f * 1024 + ct * 64 + c];
    }
    __syncthreads();
    int cg = threadIdx.x & 63;
    int rgp = threadIdx.x >> 6;
    float acc[5] = {0.f, 0.f, 0.f, 0.f, 0.f};
#pragma unroll 8
    for (int f = 0; f < 256; f++) {
        float w = ws[f * 65 + cg];
#pragma unroll
        for (int q = 0; q < 5; q++) acc[q] += hs[(rgp * 5 + q) * 256 + f] * w;
    }
    int c = ct * 64 + cg;
#pragma unroll
    for (int q = 0; q < 5; q++)
        g_ftdst[(b * NK + rgp * 5 + q) * 1024 + c] = acc[q];
}

// ---------------- A2: V reduction ----------------
#define V_SMEM_FLOATS (64 * 257 + NK * 256)
__global__ void __launch_bounds__(256) k_V(const float* __restrict__ W) {
    extern __shared__ float sm[];
    float* ws2 = sm;
    float* fts2 = sm + 64 * 257;
    int b = blockIdx.y;
    int ft = blockIdx.x >> 2, ds = blockIdx.x & 3;
    int fbase = ft * 64, dbase = ds * 64;
#pragma unroll 4
    for (int i = threadIdx.x; i < 64 * 256; i += 256) {
        int fi = i >> 8, rest = i & 255;
        int h = rest >> 6, dd = rest & 63;
        ws2[fi * 257 + rest] = W[(fbase + fi) * 1024 + h * 256 + dbase + dd];
    }
#pragma unroll 4
    for (int i = threadIdx.x; i < NK * 256; i += 256) {
        int rest = i & 255;
        int h = rest >> 6, dd = rest & 63;
        int k = i >> 8;
        fts2[i] = g_ftdst[b * 20480 + k * 1024 + h * 256 + dbase + dd];
    }
    __syncthreads();
    int fi = threadIdx.x & 63;
    int h  = threadIdx.x >> 6;
    float acc[NK];
#pragma unroll
    for (int j = 0; j < NK; j++) acc[j] = 0.f;
    const float* wp = ws2 + fi * 257 + h * 64;
    const float* fp = fts2 + h * 64;
#pragma unroll 2
    for (int dd = 0; dd < 64; dd++) {
        float w = wp[dd];
#pragma unroll
        for (int j = 0; j < NK; j++) acc[j] += w * fp[j * 256 + dd];
    }
    float* gv = g_V + b * (FF * KH) + (fbase + fi) * KH + h;
#pragma unroll
    for (int j = 0; j < NK; j++)
        atomicAdd(gv + j * 4, acc[j] * 0.0625f);
}

// ---------------- A3: build B fragments (+ zero g_S) ----------------
// frag flat index i = ((ks*10+nt)*32+lane)*2+reg per split; split1 at +10240.
__global__ void __launch_bounds__(256) k_Bfrag() {
    int b = blockIdx.x;
    int tid = threadIdx.x;
    for (int i = tid; i < NK * HH * 4; i += 256) g_S[b * 320 + i] = 0.f;
    const float* gV = g_V + b * (FF * KH);
    uint32_t* outp = g_Bfrag + b * 20480;
#pragma unroll 4
    for (int i = tid; i < 10240; i += 256) {
        int reg = i & 1;
        int lane = (i >> 1) & 31;
        int knt = i >> 6;             // ks*10 + nt
        int nt = knt % 10, ks = knt / 10;
        int g = lane >> 2, tg = lane & 3;
        int k = ks * 16 + 2 * tg + reg * 8;
        int n = nt * 8 + g;
        float v0 = gV[k * 80 + n];
        float v1 = gV[(k + 1) * 80 + n];
        uint32_t hi, lo;
        split_pack(v0, v1, hi, lo);
        outp[i] = hi;
        outp[10240 + i] = lo;
    }
}

// ---------------- B: HMMA attention  a = h @ V ; exp ; 4 moments ----------------
// grid (32, 8), 256 threads. CTA: 128 rows x 80 cols, K=256 (bf16 hi/lo split).
// Warp wid handles rows [wid*16, +16): 10 n-tiles, 16 k-steps, 3 mma per (nt,ks).
#define SM_BF   0                          // 81920 B: B fragments (hi|lo)
#define SM_XS   81920                      // 2048 B: x positions (float4 x 128)
#define SM_SME  (SM_XS + 2048)             // 41472 B: exp matrix 128x81
#define SM_RED  (SM_SME + 128 * 81 * 4)    // 2560 B: partial reductions
#define ATTN_SMEM_BYTES (SM_RED + 2560)    // 128000
__global__ void __launch_bounds__(256, 1) k_attn(const float* __restrict__ h_rec,
                                                 const float* __restrict__ x_rec) {
    extern __shared__ char smc[];
    uint32_t* bf = (uint32_t*)(smc + SM_BF);
    float4* xs = (float4*)(smc + SM_XS);
    float* sme = (float*)(smc + SM_SME);
    float* red = (float*)(smc + SM_RED);
    int b = blockIdx.y;
    int tid = threadIdx.x;
    int wid = tid >> 5, lane = tid & 31;
    int g = lane >> 2, tg = lane & 3;
    int rowbase = blockIdx.x * 128;

    // bulk copy B fragments (80KB) into smem
    {
        uint32_t bf_u32 = (uint32_t)__cvta_generic_to_shared(bf);
        const uint32_t* src = g_Bfrag + b * 20480;
#pragma unroll
        for (int q = 0; q < 20; q++) {
            int i = tid + q * 256;
            cp_async16(bf_u32 + (uint32_t)i * 16u, src + i * 4);
        }
        asm volatile("cp.async.commit_group;");
    }
    if (tid < 128) {
        const float* xp = x_rec + ((size_t)(b * NR + rowbase + tid)) * 3;
        xs[tid] = make_float4(xp[0], xp[1], xp[2], 0.f);
    }
    asm volatile("cp.async.wait_group 0;");
    __syncthreads();

    // mainloop
    const float* hp0 = h_rec + ((size_t)(b * NR + rowbase + wid * 16 + g)) * FF;
    const float* hp1 = hp0 + 8 * FF;
    int cb = 2 * tg;
    float c[10][4];
#pragma unroll
    for (int nt = 0; nt < 10; nt++)
#pragma unroll
        for (int e = 0; e < 4; e++) c[nt][e] = 0.f;

    float2 pA[2][4];
#pragma unroll
    for (int s = 0; s < 2; s++) {
        pA[s][0] = *(const float2*)(hp0 + s * 16 + cb);
        pA[s][1] = *(const float2*)(hp1 + s * 16 + cb);
        pA[s][2] = *(const float2*)(hp0 + s * 16 + cb + 8);
        pA[s][3] = *(const float2*)(hp1 + s * 16 + cb + 8);
    }

#pragma unroll 2
    for (int ks = 0; ks < 16; ks++) {
        uint32_t ah[4], al[4];
#pragma unroll
        for (int j = 0; j < 4; j++)
            split_pack(pA[ks & 1][j].x, pA[ks & 1][j].y, ah[j], al[j]);
        if (ks < 14) {
            int s = ks & 1;
#pragma unroll
            for (int j = 0; j < 4; j++) {
                const float* base = (j & 1) ? hp1 : hp0;
                pA[s][j] = *(const float2*)(base + (ks + 2) * 16 + cb + (j >> 1) * 8);
            }
        }
        const uint32_t* bfh = bf + ks * 640 + lane * 2;
        const uint32_t* bfl = bfh + 10240;
#pragma unroll
        for (int nt = 0; nt < 10; nt++) {
            uint2 bh = *(const uint2*)(bfh + nt * 64);
            uint2 bl = *(const uint2*)(bfl + nt * 64);
            mma16816(c[nt], ah, bh.x, bh.y);
            mma16816(c[nt], ah, bl.x, bl.y);
            mma16816(c[nt], al, bh.x, bh.y);
        }
    }

    // epilogue: exp into smem (row-major, pitch 81)
    {
        int r0 = wid * 16 + g, r1 = r0 + 8;
#pragma unroll
        for (int nt = 0; nt < 10; nt++) {
            int cc = nt * 8 + 2 * tg;
            sme[r0 * 81 + cc]     = expf(c[nt][0]);
            sme[r0 * 81 + cc + 1] = expf(c[nt][1]);
            sme[r1 * 81 + cc]     = expf(c[nt][2]);
            sme[r1 * 81 + cc + 1] = expf(c[nt][3]);
        }
    }
    __syncthreads();

    // column reduce: 160 threads, each sums 64 rows of one column
    if (tid < 160) {
        int col = tid >> 1, hf = tid & 1;
        float S0 = 0.f, S1 = 0.f, S2 = 0.f, S3 = 0.f;
#pragma unroll 4
        for (int r = hf * 64; r < hf * 64 + 64; r++) {
            float e = sme[r * 81 + col];
            float4 x = xs[r];
            S0 += e;
            S1 += e * x.x;
            S2 += e * x.y;
            S3 += e * x.z;
        }
        float* rp = red + tid * 4;
        rp[0] = S0; rp[1] = S1; rp[2] = S2; rp[3] = S3;
    }
    __syncthreads();
    if (tid < 80) {
        const float* r0 = red + (tid * 2) * 4;
        const float* r1 = red + (tid * 2 + 1) * 4;
        float* gs = g_S + b * 320 + tid * 4;
        atomicAdd(gs + 0, r0[0] + r1[0]);
        atomicAdd(gs + 1, r0[1] + r1[1]);
        atomicAdd(gs + 2, r0[2] + r1[2]);
        atomicAdd(gs + 3, r0[3] + r1[3]);
    }
}

// ---------------- tail: kp_pos + top-8 + gather/MLP/SiLU/LayerNorm ----------------
__global__ void __launch_bounds__(256) k_tail(const float* __restrict__ x_rec,
                                              const float* __restrict__ h_rec,
                                              const float* __restrict__ W_mlp,
                                              const float* __restrict__ b_mlp,
                                              const float* __restrict__ gamma,
                                              const float* __restrict__ beta,
                                              float* __restrict__ out) {
    __shared__ float sd[256 * KNN];
    __shared__ int   si[256 * KNN];
    __shared__ float kpos[3];
    __shared__ float hm[FF];
    __shared__ float dk8[KNN];
    __shared__ int   id8[KNN];
    __shared__ float rbuf[16];
    __shared__ float mv[2];
    int bk = blockIdx.x, b = bk / NK, tid = threadIdx.x;

    if (tid == 0) {
        float p0 = 0.f, p1 = 0.f, p2 = 0.f;
#pragma unroll
        for (int h = 0; h < HH; h++) {
            const float* S = g_S + bk * 16 + h * 4;
            float inv = 1.f / S[0];
            p0 += S[1] * inv; p1 += S[2] * inv; p2 += S[3] * inv;
        }
        p0 *= 0.25f; p1 *= 0.25f; p2 *= 0.25f;
        kpos[0] = p0; kpos[1] = p1; kpos[2] = p2;
        out[bk * 3 + 0] = p0; out[bk * 3 + 1] = p1; out[bk * 3 + 2] = p2;
    }
    __syncthreads();
    float px = kpos[0], py = kpos[1], pz = kpos[2];

    float bd[KNN]; int bi[KNN];
#pragma unroll
    for (int j = 0; j < KNN; j++) { bd[j] = 3.4e38f; bi[j] = 0x7fffffff; }
    const float* xb = x_rec + (size_t)b * NR * 3;
#pragma unroll 1
    for (int base = 0; base < NR; base += 1024) {
        float d2v[4];
#pragma unroll
        for (int u = 0; u < 4; u++) {
            int r = base + u * 256 + tid;
            float dx = xb[r * 3 + 0] - px;
            float dy = xb[r * 3 + 1] - py;
            float dz = xb[r * 3 + 2] - pz;
            d2v[u] = dx * dx + dy * dy + dz * dz;
        }
#pragma unroll
        for (int u = 0; u < 4; u++) {
            float d2 = d2v[u];
            if (d2 < bd[KNN - 1]) {
                int r = base + u * 256 + tid;
                int p = KNN - 1;
                while (p > 0 && d2 < bd[p - 1]) { bd[p] = bd[p - 1]; bi[p] = bi[p - 1]; p--; }
                bd[p] = d2; bi[p] = r;
            }
        }
    }
#pragma unroll
    for (int j = 0; j < KNN; j++) { sd[tid * KNN + j] = bd[j]; si[tid * KNN + j] = bi[j]; }
    for (int stride = 128; stride >= 1; stride >>= 1) {
        __syncthreads();
        if (tid < stride) {
            float od[KNN]; int oi[KNN];
            int ia = 0, ib = 0;
#pragma unroll
            for (int o = 0; o < KNN; o++) {
                float da = sd[tid * KNN + ia], db = sd[(tid + stride) * KNN + ib];
                int xa = si[tid * KNN + ia], xb2 = si[(tid + stride) * KNN + ib];
                bool ta = (da < db) || (da == db && xa < xb2);
                if (ta) { od[o] = da; oi[o] = xa; ia++; }
                else    { od[o] = db; oi[o] = xb2; ib++; }
            }
#pragma unroll
            for (int o = 0; o < KNN; o++) { sd[tid * KNN + o] = od[o]; si[tid * KNN + o] = oi[o]; }
        }
    }
    __syncthreads();
    if (tid < KNN) { dk8[tid] = sqrtf(sd[tid]); id8[tid] = si[tid]; }
    __syncthreads();

    int j = tid;
    float a = 0.f;
#pragma unroll
    for (int t = 0; t < KNN; t++)
        a += h_rec[((size_t)b * NR + id8[t]) * FF + j];
    hm[j] = a * 0.125f;
    __syncthreads();

    float y = b_mlp[j];
#pragma unroll 16
    for (int i = 0; i < FF; i++) y += hm[i] * W_mlp[i * FF + j];
#pragma unroll
    for (int t = 0; t < KNN; t++) y += dk8[t] * W_mlp[(FF + t) * FF + j];
    y = y / (1.f + expf(-y));

    float s1 = y, s2 = y * y;
#pragma unroll
    for (int d = 16; d; d >>= 1) {
        s1 += __shfl_down_sync(0xffffffffu, s1, d);
        s2 += __shfl_down_sync(0xffffffffu, s2, d);
    }
    int lane = j & 31, w = j >> 5;
    if (lane == 0) { rbuf[w] = s1; rbuf[8 + w] = s2; }
    __syncthreads();
    if (j == 0) {
        float sa = 0.f, sb = 0.f;
#pragma unroll
        for (int w2 = 0; w2 < 8; w2++) { sa += rbuf[w2]; sb += rbuf[8 + w2]; }
        float mu = sa * (1.f / 256.f);
        mv[0] = mu;
        mv[1] = sb * (1.f / 256.f) - mu * mu;
    }
    __syncthreads();
    float mu = mv[0];
    float inv = rsqrtf(mv[1] + 1e-5f);
    out[BB * NK * 3 + bk * FF + j] = (y - mu) * inv * gamma[j] + beta[j];
}

// ---------------- launch ----------------
extern "C" void kernel_launch(void* const* d_in, const int* in_sizes, int n_in,
                              void* d_out, int out_size) {
    const float* h_rec = (const float*)d_in[0];
    const float* x_rec = (const float*)d_in[1];
    const float* h0_kp = (const float*)d_in[2];
    const float* W_src = (const float*)d_in[3];
    const float* W_mlp = (const float*)d_in[4];
    const float* b_mlp = (const float*)d_in[5];
    const float* gamma = (const float*)d_in[6];
    const float* beta  = (const float*)d_in[7];
    float* out = (float*)d_out;

    const int v_smem = V_SMEM_FLOATS * 4;
    const int ft_smem = FT_SMEM_FLOATS * 4;
    cudaFuncSetAttribute(k_attn, cudaFuncAttributeMaxDynamicSharedMemorySize, ATTN_SMEM_BYTES);
    cudaFuncSetAttribute(k_V, cudaFuncAttributeMaxDynamicSharedMemorySize, v_smem);
    cudaFuncSetAttribute(k_ftdst, cudaFuncAttributeMaxDynamicSharedMemorySize, ft_smem);

    k_ftdst<<<dim3(16, BB), 256, ft_smem>>>(h0_kp, W_src);        // launch 1 (+zero g_V)
    k_V<<<dim3(16, BB), 256, v_smem>>>(W_src);                    // launch 2
    k_Bfrag<<<BB, 256>>>();                                        // launch 3 (+zero g_S)
    k_attn<<<dim3(32, BB), 256, ATTN_SMEM_BYTES>>>(h_rec, x_rec);  // launch 4 -> profiled
    k_tail<<<BB * NK, 256>>>(x_rec, h_rec, W_mlp, b_mlp, gamma, beta, out);
}

// round 10
// speedup vs baseline: 1.4794x; 1.0829x over previous
#include <cuda_runtime.h>
#include <cuda_bf16.h>
#include <cstdint>

// ---------------- problem constants ----------------
#define BB   8
#define NR   4096
#define NK   20
#define FF   256
#define HH   4
#define KH   80
#define KNN  8

// ---------------- device scratch ----------------
__device__ float g_ftdst[BB * NK * 1024];
__device__ float g_V[BB * FF * KH];
__device__ float g_S[BB * NK * HH * 4];
__device__ uint32_t g_Bfrag[BB * 20480];   // [b][split2][ks16][nt10][lane32][reg2]

// ---------------- helpers ----------------
__device__ __forceinline__ void cp_async16(uint32_t dst, const void* src) {
    asm volatile("cp.async.ca.shared.global [%0], [%1], 16;" :: "r"(dst), "l"(src));
}
__device__ __forceinline__ void cp_async8(uint32_t dst, const void* src) {
    asm volatile("cp.async.ca.shared.global [%0], [%1], 8;" :: "r"(dst), "l"(src));
}
// hi/lo bf16x2 split of float pair (f0 in low half)
__device__ __forceinline__ void split_pack(float f0, float f1, uint32_t& hi, uint32_t& lo) {
    uint32_t u0 = __float_as_uint(f0), u1 = __float_as_uint(f1);
    hi = (u1 & 0xFFFF0000u) | (u0 >> 16);
    float r0 = f0 - __uint_as_float(u0 & 0xFFFF0000u);
    float r1 = f1 - __uint_as_float(u1 & 0xFFFF0000u);
    asm("cvt.rn.bf16x2.f32 %0, %1, %2;" : "=r"(lo) : "f"(r1), "f"(r0));
}
__device__ __forceinline__ void mma16816(float* c, const uint32_t* a, uint32_t b0, uint32_t b1) {
    asm volatile(
        "mma.sync.aligned.m16n8k16.row.col.f32.bf16.bf16.f32 "
        "{%0,%1,%2,%3}, {%4,%5,%6,%7}, {%8,%9}, {%0,%1,%2,%3};"
        : "+f"(c[0]), "+f"(c[1]), "+f"(c[2]), "+f"(c[3])
        : "r"(a[0]), "r"(a[1]), "r"(a[2]), "r"(a[3]), "r"(b0), "r"(b1));
}

// ---------------- A1: ft_dst = h0_kp @ W_src (+ zero g_V) ----------------
#define FT_SMEM_FLOATS (NK * FF + 256 * 65)
__global__ void __launch_bounds__(256) k_ftdst(const float* __restrict__ h0,
                                               const float* __restrict__ W) {
    extern __shared__ float sm[];
    float* hs = sm;
    float* ws = sm + NK * FF;
    int b = blockIdx.y, ct = blockIdx.x;
    if (ct == 0) {
        for (int i = threadIdx.x; i < FF * KH; i += 256) g_V[b * FF * KH + i] = 0.f;
    }
    for (int i = threadIdx.x; i < NK * FF; i += 256) hs[i] = h0[b * NK * FF + i];
#pragma unroll 8
    for (int i = threadIdx.x; i < 256 * 64; i += 256) {
        int f = i >> 6, c = i & 63;
        ws[f * 65 + c] = W[f * 1024 + ct * 64 + c];
    }
    __syncthreads();
    int cg = threadIdx.x & 63;
    int rgp = threadIdx.x >> 6;
    float acc[5] = {0.f, 0.f, 0.f, 0.f, 0.f};
#pragma unroll 8
    for (int f = 0; f < 256; f++) {
        float w = ws[f * 65 + cg];
#pragma unroll
        for (int q = 0; q < 5; q++) acc[q] += hs[(rgp * 5 + q) * 256 + f] * w;
    }
    int c = ct * 64 + cg;
#pragma unroll
    for (int q = 0; q < 5; q++)
        g_ftdst[(b * NK + rgp * 5 + q) * 1024 + c] = acc[q];
}

// ---------------- A2: V reduction ----------------
#define V_SMEM_FLOATS (64 * 257 + NK * 256)
__global__ void __launch_bounds__(256) k_V(const float* __restrict__ W) {
    extern __shared__ float sm[];
    float* ws2 = sm;
    float* fts2 = sm + 64 * 257;
    int b = blockIdx.y;
    int ft = blockIdx.x >> 2, ds = blockIdx.x & 3;
    int fbase = ft * 64, dbase = ds * 64;
#pragma unroll 4
    for (int i = threadIdx.x; i < 64 * 256; i += 256) {
        int fi = i >> 8, rest = i & 255;
        int h = rest >> 6, dd = rest & 63;
        ws2[fi * 257 + rest] = W[(fbase + fi) * 1024 + h * 256 + dbase + dd];
    }
#pragma unroll 4
    for (int i = threadIdx.x; i < NK * 256; i += 256) {
        int rest = i & 255;
        int h = rest >> 6, dd = rest & 63;
        int k = i >> 8;
        fts2[i] = g_ftdst[b * 20480 + k * 1024 + h * 256 + dbase + dd];
    }
    __syncthreads();
    int fi = threadIdx.x & 63;
    int h  = threadIdx.x >> 6;
    float acc[NK];
#pragma unroll
    for (int j = 0; j < NK; j++) acc[j] = 0.f;
    const float* wp = ws2 + fi * 257 + h * 64;
    const float* fp = fts2 + h * 64;
#pragma unroll 2
    for (int dd = 0; dd < 64; dd++) {
        float w = wp[dd];
#pragma unroll
        for (int j = 0; j < NK; j++) acc[j] += w * fp[j * 256 + dd];
    }
    float* gv = g_V + b * (FF * KH) + (fbase + fi) * KH + h;
#pragma unroll
    for (int j = 0; j < NK; j++)
        atomicAdd(gv + j * 4, acc[j] * 0.0625f);
}

// ---------------- A3: build B fragments (+ zero g_S), 320 blocks ----------------
__global__ void __launch_bounds__(256) k_Bfrag() {
    int b = blockIdx.y;
    int tid = threadIdx.x;
    if (blockIdx.x == 0) {
        for (int i = tid; i < NK * HH * 4; i += 256) g_S[b * 320 + i] = 0.f;
    }
    int i = blockIdx.x * 256 + tid;          // 0..10239
    const float* gV = g_V + b * (FF * KH);
    uint32_t* outp = g_Bfrag + b * 20480;
    int reg = i & 1;
    int lane = (i >> 1) & 31;
    int knt = i >> 6;                          // ks*10 + nt
    int nt = knt % 10, ks = knt / 10;
    int g = lane >> 2, tg = lane & 3;
    int k = ks * 16 + 2 * tg + reg * 8;
    int n = nt * 8 + g;
    float v0 = gV[k * 80 + n];
    float v1 = gV[(k + 1) * 80 + n];
    uint32_t hi, lo;
    split_pack(v0, v1, hi, lo);
    outp[i] = hi;
    outp[10240 + i] = lo;
}

// ---------------- B: HMMA attention  a = h @ V ; exp ; 4 moments ----------------
// grid (32, 8), 256 threads. CTA: 128 rows x 80 cols, K=256 (bf16 hi/lo split).
// A streamed via 8B cp.async into fragment-ordered smem, double-buffered chunks
// of 32 cols. B fragments bulk-copied. Epilogue exp buffer overlays A staging.
#define SM_BF   0                            // 81920 B: B fragments (hi|lo)
#define SM_XS   81920                        // 2048 B: x positions
#define SM_SA   83968                        // 32768 B: A staging (2 x 16KB)
#define SM_SME  83968                        // overlays SA (+ extends): 41472 B
#define SM_RED  125440                       // 2560 B
#define ATTN_SMEM_BYTES 128000
__global__ void __launch_bounds__(256, 1) k_attn(const float* __restrict__ h_rec,
                                                 const float* __restrict__ x_rec) {
    extern __shared__ char smc[];
    uint32_t* bf = (uint32_t*)(smc + SM_BF);
    float4* xs = (float4*)(smc + SM_XS);
    float* sme = (float*)(smc + SM_SME);
    float* red = (float*)(smc + SM_RED);
    int b = blockIdx.y;
    int tid = threadIdx.x;
    int wid = tid >> 5, lane = tid & 31;
    int g = lane >> 2, tg = lane & 3;
    int rowbase = blockIdx.x * 128;
    const float* hblk = h_rec + ((size_t)(b * NR + rowbase)) * FF;
    uint32_t sa_u32 = (uint32_t)__cvta_generic_to_shared(smc + SM_SA);

    // A-chunk loader: chunk c covers cols [c*32, c*32+32), slots s in [0,2048)
    // s = wid_s*256 + ksl*128 + j*32 + lane_s ; 8B per slot
    auto issue_chunk = [&](int c, int buf) {
#pragma unroll
        for (int q = 0; q < 8; q++) {
            int s = tid + q * 256;
            int wid_s = s >> 8;
            int rem = s & 255;
            int ksl = rem >> 7;
            int jj = (rem >> 5) & 3;
            int ln = rem & 31;
            int gg = ln >> 2, tt = ln & 3;
            int row_local = wid_s * 16 + gg + (jj & 1) * 8;
            int col = (c * 2 + ksl) * 16 + 2 * tt + (jj >> 1) * 8;
            cp_async8(sa_u32 + (uint32_t)(buf * 16384 + s * 8),
                      hblk + (size_t)row_local * FF + col);
        }
    };

    // prologue: B fragments (80KB) + chunk 0, one commit group
    {
        uint32_t bf_u32 = (uint32_t)__cvta_generic_to_shared(bf);
        const uint32_t* src = g_Bfrag + b * 20480;
#pragma unroll
        for (int q = 0; q < 20; q++) {
            int i = tid + q * 256;
            cp_async16(bf_u32 + (uint32_t)i * 16u, src + i * 4);
        }
        issue_chunk(0, 0);
        asm volatile("cp.async.commit_group;");
    }
    if (tid < 128) {
        const float* xp = x_rec + ((size_t)(b * NR + rowbase + tid)) * 3;
        xs[tid] = make_float4(xp[0], xp[1], xp[2], 0.f);
    }
    asm volatile("cp.async.wait_group 0;");
    __syncthreads();

    float c[10][4];
#pragma unroll
    for (int nt = 0; nt < 10; nt++)
#pragma unroll
        for (int e = 0; e < 4; e++) c[nt][e] = 0.f;

#pragma unroll 1
    for (int ch = 0; ch < 8; ch++) {
        if (ch < 7) {
            issue_chunk(ch + 1, (ch + 1) & 1);
            asm volatile("cp.async.commit_group;");
            asm volatile("cp.async.wait_group 1;");
        } else {
            asm volatile("cp.async.wait_group 0;");
        }
        __syncthreads();

        const char* sab = smc + SM_SA + ((ch & 1) * 16384) + (wid * 256 + lane) * 8;
#pragma unroll
        for (int ksl = 0; ksl < 2; ksl++) {
            int ks = ch * 2 + ksl;
            uint32_t ah[4], al[4];
#pragma unroll
            for (int j = 0; j < 4; j++) {
                float2 av = *(const float2*)(sab + (ksl * 128 + j * 32) * 8);
                split_pack(av.x, av.y, ah[j], al[j]);
            }
            const uint32_t* bfh = bf + ks * 640 + lane * 2;
            const uint32_t* bfl = bfh + 10240;
#pragma unroll
            for (int nt = 0; nt < 10; nt++) {
                uint2 bh = *(const uint2*)(bfh + nt * 64);
                uint2 bl = *(const uint2*)(bfl + nt * 64);
                mma16816(c[nt], ah, bh.x, bh.y);
                mma16816(c[nt], ah, bl.x, bl.y);
                mma16816(c[nt], al, bh.x, bh.y);
            }
        }
        __syncthreads();      // buffer reuse safety (also guards sme overlay after loop)
    }

    // epilogue: exp into smem (row-major, pitch 81) — overlays dead A staging
    {
        int r0 = wid * 16 + g, r1 = r0 + 8;
#pragma unroll
        for (int nt = 0; nt < 10; nt++) {
            int cc = nt * 8 + 2 * tg;
            sme[r0 * 81 + cc]     = expf(c[nt][0]);
            sme[r0 * 81 + cc + 1] = expf(c[nt][1]);
            sme[r1 * 81 + cc]     = expf(c[nt][2]);
            sme[r1 * 81 + cc + 1] = expf(c[nt][3]);
        }
    }
    __syncthreads();

    // column reduce: 160 threads, each sums 64 rows of one column
    if (tid < 160) {
        int col = tid >> 1, hf = tid & 1;
        float S0 = 0.f, S1 = 0.f, S2 = 0.f, S3 = 0.f;
#pragma unroll 4
        for (int r = hf * 64; r < hf * 64 + 64; r++) {
            float e = sme[r * 81 + col];
            float4 x = xs[r];
            S0 += e;
            S1 += e * x.x;
            S2 += e * x.y;
            S3 += e * x.z;
        }
        float* rp = red + tid * 4;
        rp[0] = S0; rp[1] = S1; rp[2] = S2; rp[3] = S3;
    }
    __syncthreads();
    if (tid < 80) {
        const float* r0 = red + (tid * 2) * 4;
        const float* r1 = red + (tid * 2 + 1) * 4;
        float* gs = g_S + b * 320 + tid * 4;
        atomicAdd(gs + 0, r0[0] + r1[0]);
        atomicAdd(gs + 1, r0[1] + r1[1]);
        atomicAdd(gs + 2, r0[2] + r1[2]);
        atomicAdd(gs + 3, r0[3] + r1[3]);
    }
}

// ---------------- tail: kp_pos + top-8 + gather/MLP/SiLU/LayerNorm ----------------
__global__ void __launch_bounds__(256) k_tail(const float* __restrict__ x_rec,
                                              const float* __restrict__ h_rec,
                                              const float* __restrict__ W_mlp,
                                              const float* __restrict__ b_mlp,
                                              const float* __restrict__ gamma,
                                              const float* __restrict__ beta,
                                              float* __restrict__ out) {
    __shared__ float sd[256 * KNN];
    __shared__ int   si[256 * KNN];
    __shared__ float kpos[3];
    __shared__ float hm[FF];
    __shared__ float dk8[KNN];
    __shared__ int   id8[KNN];
    __shared__ float rbuf[16];
    __shared__ float mv[2];
    int bk = blockIdx.x, b = bk / NK, tid = threadIdx.x;

    if (tid == 0) {
        float p0 = 0.f, p1 = 0.f, p2 = 0.f;
#pragma unroll
        for (int h = 0; h < HH; h++) {
            const float* S = g_S + bk * 16 + h * 4;
            float inv = 1.f / S[0];
            p0 += S[1] * inv; p1 += S[2] * inv; p2 += S[3] * inv;
        }
        p0 *= 0.25f; p1 *= 0.25f; p2 *= 0.25f;
        kpos[0] = p0; kpos[1] = p1; kpos[2] = p2;
        out[bk * 3 + 0] = p0; out[bk * 3 + 1] = p1; out[bk * 3 + 2] = p2;
    }
    __syncthreads();
    float px = kpos[0], py = kpos[1], pz = kpos[2];

    float bd[KNN]; int bi[KNN];
#pragma unroll
    for (int j = 0; j < KNN; j++) { bd[j] = 3.4e38f; bi[j] = 0x7fffffff; }
    const float* xb = x_rec + (size_t)b * NR * 3;
#pragma unroll 1
    for (int base = 0; base < NR; base += 1024) {
        float d2v[4];
#pragma unroll
        for (int u = 0; u < 4; u++) {
            int r = base + u * 256 + tid;
            float dx = xb[r * 3 + 0] - px;
            float dy = xb[r * 3 + 1] - py;
            float dz = xb[r * 3 + 2] - pz;
            d2v[u] = dx * dx + dy * dy + dz * dz;
        }
#pragma unroll
        for (int u = 0; u < 4; u++) {
            float d2 = d2v[u];
            if (d2 < bd[KNN - 1]) {
                int r = base + u * 256 + tid;
                int p = KNN - 1;
                while (p > 0 && d2 < bd[p - 1]) { bd[p] = bd[p - 1]; bi[p] = bi[p - 1]; p--; }
                bd[p] = d2; bi[p] = r;
            }
        }
    }
#pragma unroll
    for (int j = 0; j < KNN; j++) { sd[tid * KNN + j] = bd[j]; si[tid * KNN + j] = bi[j]; }
    for (int stride = 128; stride >= 1; stride >>= 1) {
        __syncthreads();
        if (tid < stride) {
            float od[KNN]; int oi[KNN];
            int ia = 0, ib = 0;
#pragma unroll
            for (int o = 0; o < KNN; o++) {
                float da = sd[tid * KNN + ia], db = sd[(tid + stride) * KNN + ib];
                int xa = si[tid * KNN + ia], xb2 = si[(tid + stride) * KNN + ib];
                bool ta = (da < db) || (da == db && xa < xb2);
                if (ta) { od[o] = da; oi[o] = xa; ia++; }
                else    { od[o] = db; oi[o] = xb2; ib++; }
            }
#pragma unroll
            for (int o = 0; o < KNN; o++) { sd[tid * KNN + o] = od[o]; si[tid * KNN + o] = oi[o]; }
        }
    }
    __syncthreads();
    if (tid < KNN) { dk8[tid] = sqrtf(sd[tid]); id8[tid] = si[tid]; }
    __syncthreads();

    int j = tid;
    float a = 0.f;
#pragma unroll
    for (int t = 0; t < KNN; t++)
        a += h_rec[((size_t)b * NR + id8[t]) * FF + j];
    hm[j] = a * 0.125f;
    __syncthreads();

    // MLP with 4 independent accumulator chains
    float y0 = b_mlp[j], y1 = 0.f, y2 = 0.f, y3 = 0.f;
#pragma unroll 8
    for (int i = 0; i < FF; i += 4) {
        y0 += hm[i]     * W_mlp[i * FF + j];
        y1 += hm[i + 1] * W_mlp[(i + 1) * FF + j];
        y2 += hm[i + 2] * W_mlp[(i + 2) * FF + j];
        y3 += hm[i + 3] * W_mlp[(i + 3) * FF + j];
    }
#pragma unroll
    for (int t = 0; t < KNN; t += 2) {
        y0 += dk8[t]     * W_mlp[(FF + t) * FF + j];
        y1 += dk8[t + 1] * W_mlp[(FF + t + 1) * FF + j];
    }
    float y = (y0 + y1) + (y2 + y3);
    y = y / (1.f + expf(-y));

    float s1 = y, s2 = y * y;
#pragma unroll
    for (int d = 16; d; d >>= 1) {
        s1 += __shfl_down_sync(0xffffffffu, s1, d);
        s2 += __shfl_down_sync(0xffffffffu, s2, d);
    }
    int lane = j & 31, w = j >> 5;
    if (lane == 0) { rbuf[w] = s1; rbuf[8 + w] = s2; }
    __syncthreads();
    if (j == 0) {
        float sa = 0.f, sb = 0.f;
#pragma unroll
        for (int w2 = 0; w2 < 8; w2++) { sa += rbuf[w2]; sb += rbuf[8 + w2]; }
        float mu = sa * (1.f / 256.f);
        mv[0] = mu;
        mv[1] = sb * (1.f / 256.f) - mu * mu;
    }
    __syncthreads();
    float mu = mv[0];
    float inv = rsqrtf(mv[1] + 1e-5f);
    out[BB * NK * 3 + bk * FF + j] = (y - mu) * inv * gamma[j] + beta[j];
}

// ---------------- launch ----------------
extern "C" void kernel_launch(void* const* d_in, const int* in_sizes, int n_in,
                              void* d_out, int out_size) {
    const float* h_rec = (const float*)d_in[0];
    const float* x_rec = (const float*)d_in[1];
    const float* h0_kp = (const float*)d_in[2];
    const float* W_src = (const float*)d_in[3];
    const float* W_mlp = (const float*)d_in[4];
    const float* b_mlp = (const float*)d_in[5];
    const float* gamma = (const float*)d_in[6];
    const float* beta  = (const float*)d_in[7];
    float* out = (float*)d_out;

    const int v_smem = V_SMEM_FLOATS * 4;
    const int ft_smem = FT_SMEM_FLOATS * 4;
    cudaFuncSetAttribute(k_attn, cudaFuncAttributeMaxDynamicSharedMemorySize, ATTN_SMEM_BYTES);
    cudaFuncSetAttribute(k_V, cudaFuncAttributeMaxDynamicSharedMemorySize, v_smem);
    cudaFuncSetAttribute(k_ftdst, cudaFuncAttributeMaxDynamicSharedMemorySize, ft_smem);

    k_ftdst<<<dim3(16, BB), 256, ft_smem>>>(h0_kp, W_src);        // launch 1 (+zero g_V)
    k_V<<<dim3(16, BB), 256, v_smem>>>(W_src);                    // launch 2
    k_Bfrag<<<dim3(40, BB), 256>>>();                              // launch 3 (+zero g_S)
    k_attn<<<dim3(32, BB), 256, ATTN_SMEM_BYTES>>>(h_rec, x_rec);  // launch 4 -> profiled
    k_tail<<<BB * NK, 256>>>(x_rec, h_rec, W_mlp, b_mlp, gamma, beta, out);
}

// round 11
// speedup vs baseline: 1.5868x; 1.0726x over previous
#include <cuda_runtime.h>
#include <cuda_bf16.h>
#include <cstdint>

// ---------------- problem constants ----------------
#define BB   8
#define NR   4096
#define NK   20
#define FF   256
#define HH   4
#define KH   80
#define KNN  8

// ---------------- device scratch ----------------
__device__ float g_ftdst[BB * NK * 1024];
__device__ float g_V[BB * FF * KH];
__device__ float g_S[BB * NK * HH * 4];
__device__ uint32_t g_Bfrag[BB * 20480];   // [b][split2][ks16][nt10][lane32][reg2]

// ---------------- helpers ----------------
__device__ __forceinline__ void cp_async16(uint32_t dst, const void* src) {
    asm volatile("cp.async.ca.shared.global [%0], [%1], 16;" :: "r"(dst), "l"(src));
}
// hi/lo bf16x2 split of float pair (f0 in low half)
__device__ __forceinline__ void split_pack(float f0, float f1, uint32_t& hi, uint32_t& lo) {
    uint32_t u0 = __float_as_uint(f0), u1 = __float_as_uint(f1);
    hi = (u1 & 0xFFFF0000u) | (u0 >> 16);
    float r0 = f0 - __uint_as_float(u0 & 0xFFFF0000u);
    float r1 = f1 - __uint_as_float(u1 & 0xFFFF0000u);
    asm("cvt.rn.bf16x2.f32 %0, %1, %2;" : "=r"(lo) : "f"(r1), "f"(r0));
}
__device__ __forceinline__ void mma16816(float* c, const uint32_t* a, uint32_t b0, uint32_t b1) {
    asm volatile(
        "mma.sync.aligned.m16n8k16.row.col.f32.bf16.bf16.f32 "
        "{%0,%1,%2,%3}, {%4,%5,%6,%7}, {%8,%9}, {%0,%1,%2,%3};"
        : "+f"(c[0]), "+f"(c[1]), "+f"(c[2]), "+f"(c[3])
        : "r"(a[0]), "r"(a[1]), "r"(a[2]), "r"(a[3]), "r"(b0), "r"(b1));
}

// ---------------- A1: ft_dst = h0_kp @ W_src (+ zero g_V) ----------------
#define FT_SMEM_FLOATS (NK * FF + 256 * 65)
__global__ void __launch_bounds__(256) k_ftdst(const float* __restrict__ h0,
                                               const float* __restrict__ W) {
    extern __shared__ float sm[];
    float* hs = sm;
    float* ws = sm + NK * FF;
    int b = blockIdx.y, ct = blockIdx.x;
    if (ct == 0) {
        for (int i = threadIdx.x; i < FF * KH; i += 256) g_V[b * FF * KH + i] = 0.f;
    }
    for (int i = threadIdx.x; i < NK * FF; i += 256) hs[i] = h0[b * NK * FF + i];
#pragma unroll 8
    for (int i = threadIdx.x; i < 256 * 64; i += 256) {
        int f = i >> 6, c = i & 63;
        ws[f * 65 + c] = W[f * 1024 + ct * 64 + c];
    }
    __syncthreads();
    int cg = threadIdx.x & 63;
    int rgp = threadIdx.x >> 6;
    float acc[5] = {0.f, 0.f, 0.f, 0.f, 0.f};
#pragma unroll 8
    for (int f = 0; f < 256; f++) {
        float w = ws[f * 65 + cg];
#pragma unroll
        for (int q = 0; q < 5; q++) acc[q] += hs[(rgp * 5 + q) * 256 + f] * w;
    }
    int c = ct * 64 + cg;
#pragma unroll
    for (int q = 0; q < 5; q++)
        g_ftdst[(b * NK + rgp * 5 + q) * 1024 + c] = acc[q];
}

// ---------------- A2: V reduction ----------------
#define V_SMEM_FLOATS (64 * 257 + NK * 256)
__global__ void __launch_bounds__(256) k_V(const float* __restrict__ W) {
    extern __shared__ float sm[];
    float* ws2 = sm;
    float* fts2 = sm + 64 * 257;
    int b = blockIdx.y;
    int ft = blockIdx.x >> 2, ds = blockIdx.x & 3;
    int fbase = ft * 64, dbase = ds * 64;
#pragma unroll 4
    for (int i = threadIdx.x; i < 64 * 256; i += 256) {
        int fi = i >> 8, rest = i & 255;
        int h = rest >> 6, dd = rest & 63;
        ws2[fi * 257 + rest] = W[(fbase + fi) * 1024 + h * 256 + dbase + dd];
    }
#pragma unroll 4
    for (int i = threadIdx.x; i < NK * 256; i += 256) {
        int rest = i & 255;
        int h = rest >> 6, dd = rest & 63;
        int k = i >> 8;
        fts2[i] = g_ftdst[b * 20480 + k * 1024 + h * 256 + dbase + dd];
    }
    __syncthreads();
    int fi = threadIdx.x & 63;
    int h  = threadIdx.x >> 6;
    float acc[NK];
#pragma unroll
    for (int j = 0; j < NK; j++) acc[j] = 0.f;
    const float* wp = ws2 + fi * 257 + h * 64;
    const float* fp = fts2 + h * 64;
#pragma unroll 2
    for (int dd = 0; dd < 64; dd++) {
        float w = wp[dd];
#pragma unroll
        for (int j = 0; j < NK; j++) acc[j] += w * fp[j * 256 + dd];
    }
    float* gv = g_V + b * (FF * KH) + (fbase + fi) * KH + h;
#pragma unroll
    for (int j = 0; j < NK; j++)
        atomicAdd(gv + j * 4, acc[j] * 0.0625f);
}

// ---------------- A3: build B fragments (+ zero g_S), 320 blocks ----------------
__global__ void __launch_bounds__(256) k_Bfrag() {
    int b = blockIdx.y;
    int tid = threadIdx.x;
    if (blockIdx.x == 0) {
        for (int i = tid; i < NK * HH * 4; i += 256) g_S[b * 320 + i] = 0.f;
    }
    int i = blockIdx.x * 256 + tid;          // 0..10239
    const float* gV = g_V + b * (FF * KH);
    uint32_t* outp = g_Bfrag + b * 20480;
    int reg = i & 1;
    int lane = (i >> 1) & 31;
    int knt = i >> 6;                          // ks*10 + nt
    int nt = knt % 10, ks = knt / 10;
    int g = lane >> 2, tg = lane & 3;
    int k = ks * 16 + 2 * tg + reg * 8;
    int n = nt * 8 + g;
    float v0 = gV[k * 80 + n];
    float v1 = gV[(k + 1) * 80 + n];
    uint32_t hi, lo;
    split_pack(v0, v1, hi, lo);
    outp[i] = hi;
    outp[10240 + i] = lo;
}

// ---------------- B: HMMA attention  a = h @ V ; exp ; 4 moments ----------------
// grid (32, 8), 256 threads. CTA: 128 rows x 80 cols, K=256 (bf16 hi/lo split).
// A loaded direct from global with 4-deep register prefetch (R9 mainloop, deeper).
#define SM_BF   0                          // 81920 B: B fragments (hi|lo)
#define SM_XS   81920                      // 2048 B: x positions (float4 x 128)
#define SM_SME  (SM_XS + 2048)             // 41472 B: exp matrix 128x81
#define SM_RED  (SM_SME + 128 * 81 * 4)    // 2560 B: partial reductions
#define ATTN_SMEM_BYTES (SM_RED + 2560)    // 128000
__global__ void __launch_bounds__(256, 1) k_attn(const float* __restrict__ h_rec,
                                                 const float* __restrict__ x_rec) {
    extern __shared__ char smc[];
    uint32_t* bf = (uint32_t*)(smc + SM_BF);
    float4* xs = (float4*)(smc + SM_XS);
    float* sme = (float*)(smc + SM_SME);
    float* red = (float*)(smc + SM_RED);
    int b = blockIdx.y;
    int tid = threadIdx.x;
    int wid = tid >> 5, lane = tid & 31;
    int g = lane >> 2, tg = lane & 3;
    int rowbase = blockIdx.x * 128;

    // bulk copy B fragments (80KB) into smem
    {
        uint32_t bf_u32 = (uint32_t)__cvta_generic_to_shared(bf);
        const uint32_t* src = g_Bfrag + b * 20480;
#pragma unroll
        for (int q = 0; q < 20; q++) {
            int i = tid + q * 256;
            cp_async16(bf_u32 + (uint32_t)i * 16u, src + i * 4);
        }
        asm volatile("cp.async.commit_group;");
    }
    if (tid < 128) {
        const float* xp = x_rec + ((size_t)(b * NR + rowbase + tid)) * 3;
        xs[tid] = make_float4(xp[0], xp[1], xp[2], 0.f);
    }
    asm volatile("cp.async.wait_group 0;");
    __syncthreads();

    // mainloop: direct LDG with 4-deep register prefetch
    const float* hp0 = h_rec + ((size_t)(b * NR + rowbase + wid * 16 + g)) * FF;
    const float* hp1 = hp0 + 8 * FF;
    int cb = 2 * tg;
    float c[10][4];
#pragma unroll
    for (int nt = 0; nt < 10; nt++)
#pragma unroll
        for (int e = 0; e < 4; e++) c[nt][e] = 0.f;

    float2 pA[4][4];
#pragma unroll
    for (int s = 0; s < 4; s++) {
        pA[s][0] = *(const float2*)(hp0 + s * 16 + cb);
        pA[s][1] = *(const float2*)(hp1 + s * 16 + cb);
        pA[s][2] = *(const float2*)(hp0 + s * 16 + cb + 8);
        pA[s][3] = *(const float2*)(hp1 + s * 16 + cb + 8);
    }

#pragma unroll 4
    for (int ks = 0; ks < 16; ks++) {
        uint32_t ah[4], al[4];
#pragma unroll
        for (int j = 0; j < 4; j++)
            split_pack(pA[ks & 3][j].x, pA[ks & 3][j].y, ah[j], al[j]);
        if (ks < 12) {
            int s = ks & 3;
#pragma unroll
            for (int j = 0; j < 4; j++) {
                const float* base = (j & 1) ? hp1 : hp0;
                pA[s][j] = *(const float2*)(base + (ks + 4) * 16 + cb + (j >> 1) * 8);
            }
        }
        const uint32_t* bfh = bf + ks * 640 + lane * 2;
        const uint32_t* bfl = bfh + 10240;
#pragma unroll
        for (int nt = 0; nt < 10; nt++) {
            uint2 bh = *(const uint2*)(bfh + nt * 64);
            uint2 bl = *(const uint2*)(bfl + nt * 64);
            mma16816(c[nt], ah, bh.x, bh.y);
            mma16816(c[nt], ah, bl.x, bl.y);
            mma16816(c[nt], al, bh.x, bh.y);
        }
    }

    // epilogue: exp into smem (row-major, pitch 81)
    {
        int r0 = wid * 16 + g, r1 = r0 + 8;
#pragma unroll
        for (int nt = 0; nt < 10; nt++) {
            int cc = nt * 8 + 2 * tg;
            sme[r0 * 81 + cc]     = expf(c[nt][0]);
            sme[r0 * 81 + cc + 1] = expf(c[nt][1]);
            sme[r1 * 81 + cc]     = expf(c[nt][2]);
            sme[r1 * 81 + cc + 1] = expf(c[nt][3]);
        }
    }
    __syncthreads();

    // column reduce: 160 threads, each sums 64 rows of one column
    if (tid < 160) {
        int col = tid >> 1, hf = tid & 1;
        float S0 = 0.f, S1 = 0.f, S2 = 0.f, S3 = 0.f;
#pragma unroll 4
        for (int r = hf * 64; r < hf * 64 + 64; r++) {
            float e = sme[r * 81 + col];
            float4 x = xs[r];
            S0 += e;
            S1 += e * x.x;
            S2 += e * x.y;
            S3 += e * x.z;
        }
        float* rp = red + tid * 4;
        rp[0] = S0; rp[1] = S1; rp[2] = S2; rp[3] = S3;
    }
    __syncthreads();
    if (tid < 80) {
        const float* r0 = red + (tid * 2) * 4;
        const float* r1 = red + (tid * 2 + 1) * 4;
        float* gs = g_S + b * 320 + tid * 4;
        atomicAdd(gs + 0, r0[0] + r1[0]);
        atomicAdd(gs + 1, r0[1] + r1[1]);
        atomicAdd(gs + 2, r0[2] + r1[2]);
        atomicAdd(gs + 3, r0[3] + r1[3]);
    }
}

// ---------------- tail: kp_pos + top-8 + gather/MLP/SiLU/LayerNorm (R9 form) ----------------
__global__ void __launch_bounds__(256) k_tail(const float* __restrict__ x_rec,
                                              const float* __restrict__ h_rec,
                                              const float* __restrict__ W_mlp,
                                              const float* __restrict__ b_mlp,
                                              const float* __restrict__ gamma,
                                              const float* __restrict__ beta,
                                              float* __restrict__ out) {
    __shared__ float sd[256 * KNN];
    __shared__ int   si[256 * KNN];
    __shared__ float kpos[3];
    __shared__ float hm[FF];
    __shared__ float dk8[KNN];
    __shared__ int   id8[KNN];
    __shared__ float rbuf[16];
    __shared__ float mv[2];
    int bk = blockIdx.x, b = bk / NK, tid = threadIdx.x;

    if (tid == 0) {
        float p0 = 0.f, p1 = 0.f, p2 = 0.f;
#pragma unroll
        for (int h = 0; h < HH; h++) {
            const float* S = g_S + bk * 16 + h * 4;
            float inv = 1.f / S[0];
            p0 += S[1] * inv; p1 += S[2] * inv; p2 += S[3] * inv;
        }
        p0 *= 0.25f; p1 *= 0.25f; p2 *= 0.25f;
        kpos[0] = p0; kpos[1] = p1; kpos[2] = p2;
        out[bk * 3 + 0] = p0; out[bk * 3 + 1] = p1; out[bk * 3 + 2] = p2;
    }
    __syncthreads();
    float px = kpos[0], py = kpos[1], pz = kpos[2];

    float bd[KNN]; int bi[KNN];
#pragma unroll
    for (int j = 0; j < KNN; j++) { bd[j] = 3.4e38f; bi[j] = 0x7fffffff; }
    const float* xb = x_rec + (size_t)b * NR * 3;
#pragma unroll 1
    for (int base = 0; base < NR; base += 1024) {
        float d2v[4];
#pragma unroll
        for (int u = 0; u < 4; u++) {
            int r = base + u * 256 + tid;
            float dx = xb[r * 3 + 0] - px;
            float dy = xb[r * 3 + 1] - py;
            float dz = xb[r * 3 + 2] - pz;
            d2v[u] = dx * dx + dy * dy + dz * dz;
        }
#pragma unroll
        for (int u = 0; u < 4; u++) {
            float d2 = d2v[u];
            if (d2 < bd[KNN - 1]) {
                int r = base + u * 256 + tid;
                int p = KNN - 1;
                while (p > 0 && d2 < bd[p - 1]) { bd[p] = bd[p - 1]; bi[p] = bi[p - 1]; p--; }
                bd[p] = d2; bi[p] = r;
            }
        }
    }
#pragma unroll
    for (int j = 0; j < KNN; j++) { sd[tid * KNN + j] = bd[j]; si[tid * KNN + j] = bi[j]; }
    for (int stride = 128; stride >= 1; stride >>= 1) {
        __syncthreads();
        if (tid < stride) {
            float od[KNN]; int oi[KNN];
            int ia = 0, ib = 0;
#pragma unroll
            for (int o = 0; o < KNN; o++) {
                float da = sd[tid * KNN + ia], db = sd[(tid + stride) * KNN + ib];
                int xa = si[tid * KNN + ia], xb2 = si[(tid + stride) * KNN + ib];
                bool ta = (da < db) || (da == db && xa < xb2);
                if (ta) { od[o] = da; oi[o] = xa; ia++; }
                else    { od[o] = db; oi[o] = xb2; ib++; }
            }
#pragma unroll
            for (int o = 0; o < KNN; o++) { sd[tid * KNN + o] = od[o]; si[tid * KNN + o] = oi[o]; }
        }
    }
    __syncthreads();
    if (tid < KNN) { dk8[tid] = sqrtf(sd[tid]); id8[tid] = si[tid]; }
    __syncthreads();

    int j = tid;
    float a = 0.f;
#pragma unroll
    for (int t = 0; t < KNN; t++)
        a += h_rec[((size_t)b * NR + id8[t]) * FF + j];
    hm[j] = a * 0.125f;
    __syncthreads();

    float y = b_mlp[j];
#pragma unroll 16
    for (int i = 0; i < FF; i++) y += hm[i] * W_mlp[i * FF + j];
#pragma unroll
    for (int t = 0; t < KNN; t++) y += dk8[t] * W_mlp[(FF + t) * FF + j];
    y = y / (1.f + expf(-y));

    float s1 = y, s2 = y * y;
#pragma unroll
    for (int d = 16; d; d >>= 1) {
        s1 += __shfl_down_sync(0xffffffffu, s1, d);
        s2 += __shfl_down_sync(0xffffffffu, s2, d);
    }
    int lane = j & 31, w = j >> 5;
    if (lane == 0) { rbuf[w] = s1; rbuf[8 + w] = s2; }
    __syncthreads();
    if (j == 0) {
        float sa = 0.f, sb = 0.f;
#pragma unroll
        for (int w2 = 0; w2 < 8; w2++) { sa += rbuf[w2]; sb += rbuf[8 + w2]; }
        float mu = sa * (1.f / 256.f);
        mv[0] = mu;
        mv[1] = sb * (1.f / 256.f) - mu * mu;
    }
    __syncthreads();
    float mu = mv[0];
    float inv = rsqrtf(mv[1] + 1e-5f);
    out[BB * NK * 3 + bk * FF + j] = (y - mu) * inv * gamma[j] + beta[j];
}

// ---------------- launch ----------------
extern "C" void kernel_launch(void* const* d_in, const int* in_sizes, int n_in,
                              void* d_out, int out_size) {
    const float* h_rec = (const float*)d_in[0];
    const float* x_rec = (const float*)d_in[1];
    const float* h0_kp = (const float*)d_in[2];
    const float* W_src = (const float*)d_in[3];
    const float* W_mlp = (const float*)d_in[4];
    const float* b_mlp = (const float*)d_in[5];
    const float* gamma = (const float*)d_in[6];
    const float* beta  = (const float*)d_in[7];
    float* out = (float*)d_out;

    const int v_smem = V_SMEM_FLOATS * 4;
    const int ft_smem = FT_SMEM_FLOATS * 4;
    cudaFuncSetAttribute(k_attn, cudaFuncAttributeMaxDynamicSharedMemorySize, ATTN_SMEM_BYTES);
    cudaFuncSetAttribute(k_V, cudaFuncAttributeMaxDynamicSharedMemorySize, v_smem);
    cudaFuncSetAttribute(k_ftdst, cudaFuncAttributeMaxDynamicSharedMemorySize, ft_smem);

    k_ftdst<<<dim3(16, BB), 256, ft_smem>>>(h0_kp, W_src);        // launch 1 (+zero g_V)
    k_V<<<dim3(16, BB), 256, v_smem>>>(W_src);                    // launch 2
    k_Bfrag<<<dim3(40, BB), 256>>>();                              // launch 3 (+zero g_S)
    k_attn<<<dim3(32, BB), 256, ATTN_SMEM_BYTES>>>(h_rec, x_rec);  // launch 4 -> profiled
    k_tail<<<BB * NK, 256>>>(x_rec, h_rec, W_mlp, b_mlp, gamma, beta, out);
}

// round 12
// speedup vs baseline: 1.6381x; 1.0324x over previous
#include <cuda_runtime.h>
#include <cuda_bf16.h>
#include <cstdint>

// ---------------- problem constants ----------------
#define BB   8
#define NR   4096
#define NK   20
#define FF   256
#define HH   4
#define KH   80
#define KNN  8

// ---------------- device scratch ----------------
__device__ float g_ftdst[BB * NK * 1024];
__device__ float g_V[BB * FF * KH];
__device__ float g_S[BB * NK * HH * 4];
__device__ uint32_t g_Bfrag[BB * 20480];   // [b][split2][ks16][nt10][lane32][reg2]

// ---------------- helpers ----------------
__device__ __forceinline__ void cp_async16(uint32_t dst, const void* src) {
    asm volatile("cp.async.ca.shared.global [%0], [%1], 16;" :: "r"(dst), "l"(src));
}
// hi/lo bf16x2 split of float pair (f0 in low half)
__device__ __forceinline__ void split_pack(float f0, float f1, uint32_t& hi, uint32_t& lo) {
    uint32_t u0 = __float_as_uint(f0), u1 = __float_as_uint(f1);
    hi = (u1 & 0xFFFF0000u) | (u0 >> 16);
    float r0 = f0 - __uint_as_float(u0 & 0xFFFF0000u);
    float r1 = f1 - __uint_as_float(u1 & 0xFFFF0000u);
    asm("cvt.rn.bf16x2.f32 %0, %1, %2;" : "=r"(lo) : "f"(r1), "f"(r0));
}
__device__ __forceinline__ void mma16816(float* c, const uint32_t* a, uint32_t b0, uint32_t b1) {
    asm volatile(
        "mma.sync.aligned.m16n8k16.row.col.f32.bf16.bf16.f32 "
        "{%0,%1,%2,%3}, {%4,%5,%6,%7}, {%8,%9}, {%0,%1,%2,%3};"
        : "+f"(c[0]), "+f"(c[1]), "+f"(c[2]), "+f"(c[3])
        : "r"(a[0]), "r"(a[1]), "r"(a[2]), "r"(a[3]), "r"(b0), "r"(b1));
}

// ---------------- A1: ft_dst = h0_kp @ W_src (+ zero g_V) ----------------
#define FT_SMEM_FLOATS (NK * FF + 256 * 65)
__global__ void __launch_bounds__(256) k_ftdst(const float* __restrict__ h0,
                                               const float* __restrict__ W) {
    extern __shared__ float sm[];
    float* hs = sm;
    float* ws = sm + NK * FF;
    int b = blockIdx.y, ct = blockIdx.x;
    if (ct == 0) {
        for (int i = threadIdx.x; i < FF * KH; i += 256) g_V[b * FF * KH + i] = 0.f;
    }
    for (int i = threadIdx.x; i < NK * FF; i += 256) hs[i] = h0[b * NK * FF + i];
#pragma unroll 8
    for (int i = threadIdx.x; i < 256 * 64; i += 256) {
        int f = i >> 6, c = i & 63;
        ws[f * 65 + c] = W[f * 1024 + ct * 64 + c];
    }
    __syncthreads();
    int cg = threadIdx.x & 63;
    int rgp = threadIdx.x >> 6;
    float acc[5] = {0.f, 0.f, 0.f, 0.f, 0.f};
#pragma unroll 8
    for (int f = 0; f < 256; f++) {
        float w = ws[f * 65 + cg];
#pragma unroll
        for (int q = 0; q < 5; q++) acc[q] += hs[(rgp * 5 + q) * 256 + f] * w;
    }
    int c = ct * 64 + cg;
#pragma unroll
    for (int q = 0; q < 5; q++)
        g_ftdst[(b * NK + rgp * 5 + q) * 1024 + c] = acc[q];
}

// ---------------- A2: V reduction ----------------
#define V_SMEM_FLOATS (64 * 257 + NK * 256)
__global__ void __launch_bounds__(256) k_V(const float* __restrict__ W) {
    extern __shared__ float sm[];
    float* ws2 = sm;
    float* fts2 = sm + 64 * 257;
    int b = blockIdx.y;
    int ft = blockIdx.x >> 2, ds = blockIdx.x & 3;
    int fbase = ft * 64, dbase = ds * 64;
#pragma unroll 4
    for (int i = threadIdx.x; i < 64 * 256; i += 256) {
        int fi = i >> 8, rest = i & 255;
        int h = rest >> 6, dd = rest & 63;
        ws2[fi * 257 + rest] = W[(fbase + fi) * 1024 + h * 256 + dbase + dd];
    }
#pragma unroll 4
    for (int i = threadIdx.x; i < NK * 256; i += 256) {
        int rest = i & 255;
        int h = rest >> 6, dd = rest & 63;
        int k = i >> 8;
        fts2[i] = g_ftdst[b * 20480 + k * 1024 + h * 256 + dbase + dd];
    }
    __syncthreads();
    int fi = threadIdx.x & 63;
    int h  = threadIdx.x >> 6;
    float acc[NK];
#pragma unroll
    for (int j = 0; j < NK; j++) acc[j] = 0.f;
    const float* wp = ws2 + fi * 257 + h * 64;
    const float* fp = fts2 + h * 64;
#pragma unroll 2
    for (int dd = 0; dd < 64; dd++) {
        float w = wp[dd];
#pragma unroll
        for (int j = 0; j < NK; j++) acc[j] += w * fp[j * 256 + dd];
    }
    float* gv = g_V + b * (FF * KH) + (fbase + fi) * KH + h;
#pragma unroll
    for (int j = 0; j < NK; j++)
        atomicAdd(gv + j * 4, acc[j] * 0.0625f);
}

// ---------------- A3: build B fragments (+ zero g_S), 320 blocks ----------------
__global__ void __launch_bounds__(256) k_Bfrag() {
    int b = blockIdx.y;
    int tid = threadIdx.x;
    if (blockIdx.x == 0) {
        for (int i = tid; i < NK * HH * 4; i += 256) g_S[b * 320 + i] = 0.f;
    }
    int i = blockIdx.x * 256 + tid;          // 0..10239
    const float* gV = g_V + b * (FF * KH);
    uint32_t* outp = g_Bfrag + b * 20480;
    int reg = i & 1;
    int lane = (i >> 1) & 31;
    int knt = i >> 6;                          // ks*10 + nt
    int nt = knt % 10, ks = knt / 10;
    int g = lane >> 2, tg = lane & 3;
    int k = ks * 16 + 2 * tg + reg * 8;
    int n = nt * 8 + g;
    float v0 = gV[k * 80 + n];
    float v1 = gV[(k + 1) * 80 + n];
    uint32_t hi, lo;
    split_pack(v0, v1, hi, lo);
    outp[i] = hi;
    outp[10240 + i] = lo;
}

// ---------------- B: HMMA attention  a = h @ V ; exp ; 4 moments ----------------
// grid (16, 8) = 128 CTAs (1 wave), 512 threads (16 warps, 4/SMSP), 256 rows/CTA.
// Warp wid: rows [wid*16, +16). Epilogue: warp-shuffle moment reduction (no sme).
#define SM_BF   0                          // 81920 B: B fragments (hi|lo)
#define SM_XS   81920                      // 4096 B: x positions (float4 x 256)
#define SM_RED  (SM_XS + 4096)             // 20480 B: 16 warps x 320 floats
#define ATTN_SMEM_BYTES (SM_RED + 20480)   // 106496
__global__ void __launch_bounds__(512, 1) k_attn(const float* __restrict__ h_rec,
                                                 const float* __restrict__ x_rec) {
    extern __shared__ char smc[];
    uint32_t* bf = (uint32_t*)(smc + SM_BF);
    float4* xs = (float4*)(smc + SM_XS);
    float* red = (float*)(smc + SM_RED);
    int b = blockIdx.y;
    int tid = threadIdx.x;
    int wid = tid >> 5, lane = tid & 31;
    int g = lane >> 2, tg = lane & 3;
    int rowbase = blockIdx.x * 256;

    // bulk copy B fragments (80KB) into smem
    {
        uint32_t bf_u32 = (uint32_t)__cvta_generic_to_shared(bf);
        const uint32_t* src = g_Bfrag + b * 20480;
#pragma unroll
        for (int q = 0; q < 10; q++) {
            int i = tid + q * 512;
            cp_async16(bf_u32 + (uint32_t)i * 16u, src + i * 4);
        }
        asm volatile("cp.async.commit_group;");
    }
    if (tid < 256) {
        const float* xp = x_rec + ((size_t)(b * NR + rowbase + tid)) * 3;
        xs[tid] = make_float4(xp[0], xp[1], xp[2], 0.f);
    }
    asm volatile("cp.async.wait_group 0;");
    __syncthreads();

    // mainloop: direct LDG with 2-deep register prefetch
    const float* hp0 = h_rec + ((size_t)(b * NR + rowbase + wid * 16 + g)) * FF;
    const float* hp1 = hp0 + 8 * FF;
    int cb = 2 * tg;
    float c[10][4];
#pragma unroll
    for (int nt = 0; nt < 10; nt++)
#pragma unroll
        for (int e = 0; e < 4; e++) c[nt][e] = 0.f;

    float2 pA[2][4];
#pragma unroll
    for (int s = 0; s < 2; s++) {
        pA[s][0] = *(const float2*)(hp0 + s * 16 + cb);
        pA[s][1] = *(const float2*)(hp1 + s * 16 + cb);
        pA[s][2] = *(const float2*)(hp0 + s * 16 + cb + 8);
        pA[s][3] = *(const float2*)(hp1 + s * 16 + cb + 8);
    }

#pragma unroll 2
    for (int ks = 0; ks < 16; ks++) {
        uint32_t ah[4], al[4];
#pragma unroll
        for (int j = 0; j < 4; j++)
            split_pack(pA[ks & 1][j].x, pA[ks & 1][j].y, ah[j], al[j]);
        if (ks < 14) {
            int s = ks & 1;
#pragma unroll
            for (int j = 0; j < 4; j++) {
                const float* base = (j & 1) ? hp1 : hp0;
                pA[s][j] = *(const float2*)(base + (ks + 2) * 16 + cb + (j >> 1) * 8);
            }
        }
        const uint32_t* bfh = bf + ks * 640 + lane * 2;
        const uint32_t* bfl = bfh + 10240;
#pragma unroll
        for (int nt = 0; nt < 10; nt++) {
            uint2 bh = *(const uint2*)(bfh + nt * 64);
            uint2 bl = *(const uint2*)(bfl + nt * 64);
            mma16816(c[nt], ah, bh.x, bh.y);
            mma16816(c[nt], ah, bl.x, bl.y);
            mma16816(c[nt], al, bh.x, bh.y);
        }
    }

    // epilogue: per-warp shuffle moment reduction
    {
        float4 x0 = xs[wid * 16 + g];
        float4 x1 = xs[wid * 16 + g + 8];
#pragma unroll
        for (int nt = 0; nt < 10; nt++) {
#pragma unroll
            for (int sub = 0; sub < 2; sub++) {
                float e0 = expf(c[nt][sub]);        // row r0, col +sub
                float e1 = expf(c[nt][2 + sub]);    // row r1, col +sub
                float v0 = e0 + e1;
                float v1 = e0 * x0.x + e1 * x1.x;
                float v2 = e0 * x0.y + e1 * x1.y;
                float v3 = e0 * x0.z + e1 * x1.z;
                // reduce over g (lanes stride 4): shfl down 16, 8, 4
#pragma unroll
                for (int d = 16; d >= 4; d >>= 1) {
                    v0 += __shfl_down_sync(0xffffffffu, v0, d);
                    v1 += __shfl_down_sync(0xffffffffu, v1, d);
                    v2 += __shfl_down_sync(0xffffffffu, v2, d);
                    v3 += __shfl_down_sync(0xffffffffu, v3, d);
                }
                if (lane < 4) {
                    int cc = nt * 8 + 2 * lane + sub;   // lane == tg for lanes 0-3
                    float* rp = red + wid * 320 + cc * 4;
                    rp[0] = v0; rp[1] = v1; rp[2] = v2; rp[3] = v3;
                }
            }
        }
    }
    __syncthreads();
    for (int v = tid; v < 320; v += 512) {
        float sum = 0.f;
#pragma unroll
        for (int w2 = 0; w2 < 16; w2++) sum += red[w2 * 320 + v];
        atomicAdd(&g_S[b * 320 + v], sum);
    }
}

// ---------------- tail: kp_pos + top-8 + gather/MLP/SiLU/LayerNorm ----------------
__global__ void __launch_bounds__(256) k_tail(const float* __restrict__ x_rec,
                                              const float* __restrict__ h_rec,
                                              const float* __restrict__ W_mlp,
                                              const float* __restrict__ b_mlp,
                                              const float* __restrict__ gamma,
                                              const float* __restrict__ beta,
                                              float* __restrict__ out) {
    __shared__ float sd[256 * KNN];
    __shared__ int   si[256 * KNN];
    __shared__ float kpos[3];
    __shared__ float hm[FF];
    __shared__ float dk8[KNN];
    __shared__ int   id8[KNN];
    __shared__ float rbuf[16];
    __shared__ float mv[2];
    int bk = blockIdx.x, b = bk / NK, tid = threadIdx.x;

    if (tid == 0) {
        float p0 = 0.f, p1 = 0.f, p2 = 0.f;
#pragma unroll
        for (int h = 0; h < HH; h++) {
            const float* S = g_S + bk * 16 + h * 4;
            float inv = 1.f / S[0];
            p0 += S[1] * inv; p1 += S[2] * inv; p2 += S[3] * inv;
        }
        p0 *= 0.25f; p1 *= 0.25f; p2 *= 0.25f;
        kpos[0] = p0; kpos[1] = p1; kpos[2] = p2;
        out[bk * 3 + 0] = p0; out[bk * 3 + 1] = p1; out[bk * 3 + 2] = p2;
    }
    __syncthreads();
    float px = kpos[0], py = kpos[1], pz = kpos[2];

    float bd[KNN]; int bi[KNN];
#pragma unroll
    for (int j = 0; j < KNN; j++) { bd[j] = 3.4e38f; bi[j] = 0x7fffffff; }
    const float* xb = x_rec + (size_t)b * NR * 3;
#pragma unroll 1
    for (int base = 0; base < NR; base += 1024) {
        float d2v[4];
#pragma unroll
        for (int u = 0; u < 4; u++) {
            int r = base + u * 256 + tid;
            float dx = xb[r * 3 + 0] - px;
            float dy = xb[r * 3 + 1] - py;
            float dz = xb[r * 3 + 2] - pz;
            d2v[u] = dx * dx + dy * dy + dz * dz;
        }
#pragma unroll
        for (int u = 0; u < 4; u++) {
            float d2 = d2v[u];
            if (d2 < bd[KNN - 1]) {
                int r = base + u * 256 + tid;
                int p = KNN - 1;
                while (p > 0 && d2 < bd[p - 1]) { bd[p] = bd[p - 1]; bi[p] = bi[p - 1]; p--; }
                bd[p] = d2; bi[p] = r;
            }
        }
    }
#pragma unroll
    for (int j = 0; j < KNN; j++) { sd[tid * KNN + j] = bd[j]; si[tid * KNN + j] = bi[j]; }
    for (int stride = 128; stride >= 1; stride >>= 1) {
        __syncthreads();
        if (tid < stride) {
            float od[KNN]; int oi[KNN];
            int ia = 0, ib = 0;
#pragma unroll
            for (int o = 0; o < KNN; o++) {
                float da = sd[tid * KNN + ia], db = sd[(tid + stride) * KNN + ib];
                int xa = si[tid * KNN + ia], xb2 = si[(tid + stride) * KNN + ib];
                bool ta = (da < db) || (da == db && xa < xb2);
                if (ta) { od[o] = da; oi[o] = xa; ia++; }
                else    { od[o] = db; oi[o] = xb2; ib++; }
            }
#pragma unroll
            for (int o = 0; o < KNN; o++) { sd[tid * KNN + o] = od[o]; si[tid * KNN + o] = oi[o]; }
        }
    }
    __syncthreads();
    if (tid < KNN) { dk8[tid] = sqrtf(sd[tid]); id8[tid] = si[tid]; }
    __syncthreads();

    int j = tid;
    float a = 0.f;
#pragma unroll
    for (int t = 0; t < KNN; t++)
        a += h_rec[((size_t)b * NR + id8[t]) * FF + j];
    hm[j] = a * 0.125f;
    __syncthreads();

    float y = b_mlp[j];
#pragma unroll 16
    for (int i = 0; i < FF; i++) y += hm[i] * W_mlp[i * FF + j];
#pragma unroll
    for (int t = 0; t < KNN; t++) y += dk8[t] * W_mlp[(FF + t) * FF + j];
    y = y / (1.f + expf(-y));

    float s1 = y, s2 = y * y;
#pragma unroll
    for (int d = 16; d; d >>= 1) {
        s1 += __shfl_down_sync(0xffffffffu, s1, d);
        s2 += __shfl_down_sync(0xffffffffu, s2, d);
    }
    int lane = j & 31, w = j >> 5;
    if (lane == 0) { rbuf[w] = s1; rbuf[8 + w] = s2; }
    __syncthreads();
    if (j == 0) {
        float sa = 0.f, sb = 0.f;
#pragma unroll
        for (int w2 = 0; w2 < 8; w2++) { sa += rbuf[w2]; sb += rbuf[8 + w2]; }
        float mu = sa * (1.f / 256.f);
        mv[0] = mu;
        mv[1] = sb * (1.f / 256.f) - mu * mu;
    }
    __syncthreads();
    float mu = mv[0];
    float inv = rsqrtf(mv[1] + 1e-5f);
    out[BB * NK * 3 + bk * FF + j] = (y - mu) * inv * gamma[j] + beta[j];
}

// ---------------- launch ----------------
extern "C" void kernel_launch(void* const* d_in, const int* in_sizes, int n_in,
                              void* d_out, int out_size) {
    const float* h_rec = (const float*)d_in[0];
    const float* x_rec = (const float*)d_in[1];
    const float* h0_kp = (const float*)d_in[2];
    const float* W_src = (const float*)d_in[3];
    const float* W_mlp = (const float*)d_in[4];
    const float* b_mlp = (const float*)d_in[5];
    const float* gamma = (const float*)d_in[6];
    const float* beta  = (const float*)d_in[7];
    float* out = (float*)d_out;

    const int v_smem = V_SMEM_FLOATS * 4;
    const int ft_smem = FT_SMEM_FLOATS * 4;
    cudaFuncSetAttribute(k_attn, cudaFuncAttributeMaxDynamicSharedMemorySize, ATTN_SMEM_BYTES);
    cudaFuncSetAttribute(k_V, cudaFuncAttributeMaxDynamicSharedMemorySize, v_smem);
    cudaFuncSetAttribute(k_ftdst, cudaFuncAttributeMaxDynamicSharedMemorySize, ft_smem);

    k_ftdst<<<dim3(16, BB), 256, ft_smem>>>(h0_kp, W_src);        // launch 1 (+zero g_V)
    k_V<<<dim3(16, BB), 256, v_smem>>>(W_src);                    // launch 2
    k_Bfrag<<<dim3(40, BB), 256>>>();                              // launch 3 (+zero g_S)
    k_attn<<<dim3(16, BB), 512, ATTN_SMEM_BYTES>>>(h_rec, x_rec);  // launch 4 -> profiled
    k_tail<<<BB * NK, 256>>>(x_rec, h_rec, W_mlp, b_mlp, gamma, beta, out);
}

// round 13
// speedup vs baseline: 1.6476x; 1.0058x over previous
#include <cuda_runtime.h>
#include <cuda_bf16.h>
#include <cstdint>

// ---------------- problem constants ----------------
#define BB   8
#define NR   4096
#define NK   20
#define FF   256
#define HH   4
#define KH   80
#define KNN  8

// ---------------- device scratch ----------------
__device__ float g_ftdst[BB * NK * 1024];
__device__ float g_V[BB * FF * KH];
__device__ float g_S[BB * NK * HH * 4];

// ---------------- helpers ----------------
// hi/lo bf16x2 split of float pair (f0 in low half)
__device__ __forceinline__ void split_pack(float f0, float f1, uint32_t& hi, uint32_t& lo) {
    uint32_t u0 = __float_as_uint(f0), u1 = __float_as_uint(f1);
    hi = (u1 & 0xFFFF0000u) | (u0 >> 16);
    float r0 = f0 - __uint_as_float(u0 & 0xFFFF0000u);
    float r1 = f1 - __uint_as_float(u1 & 0xFFFF0000u);
    asm("cvt.rn.bf16x2.f32 %0, %1, %2;" : "=r"(lo) : "f"(r1), "f"(r0));
}
__device__ __forceinline__ void mma16816(float* c, const uint32_t* a, uint32_t b0, uint32_t b1) {
    asm volatile(
        "mma.sync.aligned.m16n8k16.row.col.f32.bf16.bf16.f32 "
        "{%0,%1,%2,%3}, {%4,%5,%6,%7}, {%8,%9}, {%0,%1,%2,%3};"
        : "+f"(c[0]), "+f"(c[1]), "+f"(c[2]), "+f"(c[3])
        : "r"(a[0]), "r"(a[1]), "r"(a[2]), "r"(a[3]), "r"(b0), "r"(b1));
}

// ---------------- A1: ft_dst = h0_kp @ W_src (+ zero g_V, g_S) ----------------
#define FT_SMEM_FLOATS (NK * FF + 256 * 65)
__global__ void __launch_bounds__(256) k_ftdst(const float* __restrict__ h0,
                                               const float* __restrict__ W) {
    extern __shared__ float sm[];
    float* hs = sm;
    float* ws = sm + NK * FF;
    int b = blockIdx.y, ct = blockIdx.x;
    if (ct == 0) {
        for (int i = threadIdx.x; i < FF * KH; i += 256) g_V[b * FF * KH + i] = 0.f;
        for (int i = threadIdx.x; i < NK * HH * 4; i += 256) g_S[b * NK * HH * 4 + i] = 0.f;
    }
    for (int i = threadIdx.x; i < NK * FF; i += 256) hs[i] = h0[b * NK * FF + i];
#pragma unroll 8
    for (int i = threadIdx.x; i < 256 * 64; i += 256) {
        int f = i >> 6, c = i & 63;
        ws[f * 65 + c] = W[f * 1024 + ct * 64 + c];
    }
    __syncthreads();
    int cg = threadIdx.x & 63;
    int rgp = threadIdx.x >> 6;
    float acc[5] = {0.f, 0.f, 0.f, 0.f, 0.f};
#pragma unroll 8
    for (int f = 0; f < 256; f++) {
        float w = ws[f * 65 + cg];
#pragma unroll
        for (int q = 0; q < 5; q++) acc[q] += hs[(rgp * 5 + q) * 256 + f] * w;
    }
    int c = ct * 64 + cg;
#pragma unroll
    for (int q = 0; q < 5; q++)
        g_ftdst[(b * NK + rgp * 5 + q) * 1024 + c] = acc[q];
}

// ---------------- A2: V reduction ----------------
#define V_SMEM_FLOATS (64 * 257 + NK * 256)
__global__ void __launch_bounds__(256) k_V(const float* __restrict__ W) {
    extern __shared__ float sm[];
    float* ws2 = sm;
    float* fts2 = sm + 64 * 257;
    int b = blockIdx.y;
    int ft = blockIdx.x >> 2, ds = blockIdx.x & 3;
    int fbase = ft * 64, dbase = ds * 64;
#pragma unroll 4
    for (int i = threadIdx.x; i < 64 * 256; i += 256) {
        int fi = i >> 8, rest = i & 255;
        int h = rest >> 6, dd = rest & 63;
        ws2[fi * 257 + rest] = W[(fbase + fi) * 1024 + h * 256 + dbase + dd];
    }
#pragma unroll 4
    for (int i = threadIdx.x; i < NK * 256; i += 256) {
        int rest = i & 255;
        int h = rest >> 6, dd = rest & 63;
        int k = i >> 8;
        fts2[i] = g_ftdst[b * 20480 + k * 1024 + h * 256 + dbase + dd];
    }
    __syncthreads();
    int fi = threadIdx.x & 63;
    int h  = threadIdx.x >> 6;
    float acc[NK];
#pragma unroll
    for (int j = 0; j < NK; j++) acc[j] = 0.f;
    const float* wp = ws2 + fi * 257 + h * 64;
    const float* fp = fts2 + h * 64;
#pragma unroll 2
    for (int dd = 0; dd < 64; dd++) {
        float w = wp[dd];
#pragma unroll
        for (int j = 0; j < NK; j++) acc[j] += w * fp[j * 256 + dd];
    }
    float* gv = g_V + b * (FF * KH) + (fbase + fi) * KH + h;
#pragma unroll
    for (int j = 0; j < NK; j++)
        atomicAdd(gv + j * 4, acc[j] * 0.0625f);
}

// ---------------- B: HMMA attention  a = h @ V ; exp ; 4 moments ----------------
// grid (16, 8) = 128 CTAs (1 wave), 512 threads (16 warps, 4/SMSP), 256 rows/CTA.
// B fragments built in-prologue from g_V (L2-hot). Epilogue: shuffle reduction.
#define SM_BF   0                          // 81920 B: B fragments (hi|lo)
#define SM_XS   81920                      // 4096 B: x positions (float4 x 256)
#define SM_RED  (SM_XS + 4096)             // 20480 B: 16 warps x 320 floats
#define ATTN_SMEM_BYTES (SM_RED + 20480)   // 106496
__global__ void __launch_bounds__(512, 1) k_attn(const float* __restrict__ h_rec,
                                                 const float* __restrict__ x_rec) {
    extern __shared__ char smc[];
    uint32_t* bf = (uint32_t*)(smc + SM_BF);
    float4* xs = (float4*)(smc + SM_XS);
    float* red = (float*)(smc + SM_RED);
    int b = blockIdx.y;
    int tid = threadIdx.x;
    int wid = tid >> 5, lane = tid & 31;
    int g = lane >> 2, tg = lane & 3;
    int rowbase = blockIdx.x * 256;

    // build B fragments in smem directly from g_V
    {
        const float* gV = g_V + b * (FF * KH);
#pragma unroll
        for (int q = 0; q < 20; q++) {
            int i = tid + q * 512;
            int reg = i & 1;
            int l2 = (i >> 1) & 31;
            int knt = i >> 6;
            int nt = knt % 10, ks = knt / 10;
            int g2 = l2 >> 2, t2 = l2 & 3;
            int k = ks * 16 + 2 * t2 + reg * 8;
            int n = nt * 8 + g2;
            float v0 = __ldg(gV + k * 80 + n);
            float v1 = __ldg(gV + (k + 1) * 80 + n);
            uint32_t hi, lo;
            split_pack(v0, v1, hi, lo);
            bf[i] = hi;
            bf[10240 + i] = lo;
        }
    }
    if (tid < 256) {
        const float* xp = x_rec + ((size_t)(b * NR + rowbase + tid)) * 3;
        xs[tid] = make_float4(xp[0], xp[1], xp[2], 0.f);
    }
    __syncthreads();

    // mainloop: direct LDG with 2-deep register prefetch
    const float* hp0 = h_rec + ((size_t)(b * NR + rowbase + wid * 16 + g)) * FF;
    const float* hp1 = hp0 + 8 * FF;
    int cb = 2 * tg;
    float c[10][4];
#pragma unroll
    for (int nt = 0; nt < 10; nt++)
#pragma unroll
        for (int e = 0; e < 4; e++) c[nt][e] = 0.f;

    float2 pA[2][4];
#pragma unroll
    for (int s = 0; s < 2; s++) {
        pA[s][0] = *(const float2*)(hp0 + s * 16 + cb);
        pA[s][1] = *(const float2*)(hp1 + s * 16 + cb);
        pA[s][2] = *(const float2*)(hp0 + s * 16 + cb + 8);
        pA[s][3] = *(const float2*)(hp1 + s * 16 + cb + 8);
    }

#pragma unroll 2
    for (int ks = 0; ks < 16; ks++) {
        uint32_t ah[4], al[4];
#pragma unroll
        for (int j = 0; j < 4; j++)
            split_pack(pA[ks & 1][j].x, pA[ks & 1][j].y, ah[j], al[j]);
        if (ks < 14) {
            int s = ks & 1;
#pragma unroll
            for (int j = 0; j < 4; j++) {
                const float* base = (j & 1) ? hp1 : hp0;
                pA[s][j] = *(const float2*)(base + (ks + 2) * 16 + cb + (j >> 1) * 8);
            }
        }
        const uint32_t* bfh = bf + ks * 640 + lane * 2;
        const uint32_t* bfl = bfh + 10240;
#pragma unroll
        for (int nt = 0; nt < 10; nt++) {
            uint2 bh = *(const uint2*)(bfh + nt * 64);
            uint2 bl = *(const uint2*)(bfl + nt * 64);
            mma16816(c[nt], ah, bh.x, bh.y);
            mma16816(c[nt], ah, bl.x, bl.y);
            mma16816(c[nt], al, bh.x, bh.y);
        }
    }

    // epilogue: per-warp shuffle moment reduction
    {
        float4 x0 = xs[wid * 16 + g];
        float4 x1 = xs[wid * 16 + g + 8];
#pragma unroll
        for (int nt = 0; nt < 10; nt++) {
#pragma unroll
            for (int sub = 0; sub < 2; sub++) {
                float e0 = expf(c[nt][sub]);
                float e1 = expf(c[nt][2 + sub]);
                float v0 = e0 + e1;
                float v1 = e0 * x0.x + e1 * x1.x;
                float v2 = e0 * x0.y + e1 * x1.y;
                float v3 = e0 * x0.z + e1 * x1.z;
#pragma unroll
                for (int d = 16; d >= 4; d >>= 1) {
                    v0 += __shfl_down_sync(0xffffffffu, v0, d);
                    v1 += __shfl_down_sync(0xffffffffu, v1, d);
                    v2 += __shfl_down_sync(0xffffffffu, v2, d);
                    v3 += __shfl_down_sync(0xffffffffu, v3, d);
                }
                if (lane < 4) {
                    int cc = nt * 8 + 2 * lane + sub;
                    float* rp = red + wid * 320 + cc * 4;
                    rp[0] = v0; rp[1] = v1; rp[2] = v2; rp[3] = v3;
                }
            }
        }
    }
    __syncthreads();
    for (int v = tid; v < 320; v += 512) {
        float sum = 0.f;
#pragma unroll
        for (int w2 = 0; w2 < 16; w2++) sum += red[w2 * 320 + v];
        atomicAdd(&g_S[b * 320 + v], sum);
    }
}

// ---------------- tail: kp_pos + top-8 + gather/MLP/SiLU/LayerNorm ----------------
__global__ void __launch_bounds__(256) k_tail(const float* __restrict__ x_rec,
                                              const float* __restrict__ h_rec,
                                              const float* __restrict__ W_mlp,
                                              const float* __restrict__ b_mlp,
                                              const float* __restrict__ gamma,
                                              const float* __restrict__ beta,
                                              float* __restrict__ out) {
    __shared__ float sd[256 * KNN];
    __shared__ int   si[256 * KNN];
    __shared__ float kpos[3];
    __shared__ float hm[FF];
    __shared__ float dk8[KNN];
    __shared__ int   id8[KNN];
    __shared__ float rbuf[16];
    __shared__ float mv[2];
    int bk = blockIdx.x, b = bk / NK, tid = threadIdx.x;

    if (tid == 0) {
        float p0 = 0.f, p1 = 0.f, p2 = 0.f;
#pragma unroll
        for (int h = 0; h < HH; h++) {
            const float* S = g_S + bk * 16 + h * 4;
            float inv = 1.f / S[0];
            p0 += S[1] * inv; p1 += S[2] * inv; p2 += S[3] * inv;
        }
        p0 *= 0.25f; p1 *= 0.25f; p2 *= 0.25f;
        kpos[0] = p0; kpos[1] = p1; kpos[2] = p2;
        out[bk * 3 + 0] = p0; out[bk * 3 + 1] = p1; out[bk * 3 + 2] = p2;
    }
    __syncthreads();
    float px = kpos[0], py = kpos[1], pz = kpos[2];

    float bd[KNN]; int bi[KNN];
#pragma unroll
    for (int j = 0; j < KNN; j++) { bd[j] = 3.4e38f; bi[j] = 0x7fffffff; }
    const float* xb = x_rec + (size_t)b * NR * 3;
#pragma unroll 1
    for (int base = 0; base < NR; base += 1024) {
        float d2v[4];
#pragma unroll
        for (int u = 0; u < 4; u++) {
            int r = base + u * 256 + tid;
            float dx = xb[r * 3 + 0] - px;
            float dy = xb[r * 3 + 1] - py;
            float dz = xb[r * 3 + 2] - pz;
            d2v[u] = dx * dx + dy * dy + dz * dz;
        }
#pragma unroll
        for (int u = 0; u < 4; u++) {
            float d2 = d2v[u];
            if (d2 < bd[KNN - 1]) {
                int r = base + u * 256 + tid;
                int p = KNN - 1;
                while (p > 0 && d2 < bd[p - 1]) { bd[p] = bd[p - 1]; bi[p] = bi[p - 1]; p--; }
                bd[p] = d2; bi[p] = r;
            }
        }
    }
#pragma unroll
    for (int j = 0; j < KNN; j++) { sd[tid * KNN + j] = bd[j]; si[tid * KNN + j] = bi[j]; }
    for (int stride = 128; stride >= 1; stride >>= 1) {
        __syncthreads();
        if (tid < stride) {
            float od[KNN]; int oi[KNN];
            int ia = 0, ib = 0;
#pragma unroll
            for (int o = 0; o < KNN; o++) {
                float da = sd[tid * KNN + ia], db = sd[(tid + stride) * KNN + ib];
                int xa = si[tid * KNN + ia], xb2 = si[(tid + stride) * KNN + ib];
                bool ta = (da < db) || (da == db && xa < xb2);
                if (ta) { od[o] = da; oi[o] = xa; ia++; }
                else    { od[o] = db; oi[o] = xb2; ib++; }
            }
#pragma unroll
            for (int o = 0; o < KNN; o++) { sd[tid * KNN + o] = od[o]; si[tid * KNN + o] = oi[o]; }
        }
    }
    __syncthreads();
    if (tid < KNN) { dk8[tid] = sqrtf(sd[tid]); id8[tid] = si[tid]; }
    __syncthreads();

    int j = tid;
    float a = 0.f;
#pragma unroll
    for (int t = 0; t < KNN; t++)
        a += h_rec[((size_t)b * NR + id8[t]) * FF + j];
    hm[j] = a * 0.125f;
    __syncthreads();

    float y = b_mlp[j];
#pragma unroll 16
    for (int i = 0; i < FF; i++) y += hm[i] * W_mlp[i * FF + j];
#pragma unroll
    for (int t = 0; t < KNN; t++) y += dk8[t] * W_mlp[(FF + t) * FF + j];
    y = y / (1.f + expf(-y));

    float s1 = y, s2 = y * y;
#pragma unroll
    for (int d = 16; d; d >>= 1) {
        s1 += __shfl_down_sync(0xffffffffu, s1, d);
        s2 += __shfl_down_sync(0xffffffffu, s2, d);
    }
    int lane = j & 31, w = j >> 5;
    if (lane == 0) { rbuf[w] = s1; rbuf[8 + w] = s2; }
    __syncthreads();
    if (j == 0) {
        float sa = 0.f, sb = 0.f;
#pragma unroll
        for (int w2 = 0; w2 < 8; w2++) { sa += rbuf[w2]; sb += rbuf[8 + w2]; }
        float mu = sa * (1.f / 256.f);
        mv[0] = mu;
        mv[1] = sb * (1.f / 256.f) - mu * mu;
    }
    __syncthreads();
    float mu = mv[0];
    float inv = rsqrtf(mv[1] + 1e-5f);
    out[BB * NK * 3 + bk * FF + j] = (y - mu) * inv * gamma[j] + beta[j];
}

// ---------------- launch ----------------
extern "C" void kernel_launch(void* const* d_in, const int* in_sizes, int n_in,
                              void* d_out, int out_size) {
    const float* h_rec = (const float*)d_in[0];
    const float* x_rec = (const float*)d_in[1];
    const float* h0_kp = (const float*)d_in[2];
    const float* W_src = (const float*)d_in[3];
    const float* W_mlp = (const float*)d_in[4];
    const float* b_mlp = (const float*)d_in[5];
    const float* gamma = (const float*)d_in[6];
    const float* beta  = (const float*)d_in[7];
    float* out = (float*)d_out;

    const int v_smem = V_SMEM_FLOATS * 4;
    const int ft_smem = FT_SMEM_FLOATS * 4;
    cudaFuncSetAttribute(k_attn, cudaFuncAttributeMaxDynamicSharedMemorySize, ATTN_SMEM_BYTES);
    cudaFuncSetAttribute(k_V, cudaFuncAttributeMaxDynamicSharedMemorySize, v_smem);
    cudaFuncSetAttribute(k_ftdst, cudaFuncAttributeMaxDynamicSharedMemorySize, ft_smem);

    k_ftdst<<<dim3(16, BB), 256, ft_smem>>>(h0_kp, W_src);        // launch 1 (+zero g_V,g_S)
    k_V<<<dim3(16, BB), 256, v_smem>>>(W_src);                    // launch 2
    k_attn<<<dim3(16, BB), 512, ATTN_SMEM_BYTES>>>(h_rec, x_rec); // launch 3
    k_tail<<<BB * NK, 256>>>(x_rec, h_rec, W_mlp, b_mlp, gamma, beta, out);  // launch 4 -> profiled
}

// round 14
// speedup vs baseline: 1.6860x; 1.0233x over previous
#include <cuda_runtime.h>
#include <cuda_bf16.h>
#include <cstdint>

// ---------------- problem constants ----------------
#define BB   8
#define NR   4096
#define NK   20
#define FF   256
#define HH   4
#define KH   80
#define KNN  8

// ---------------- device scratch ----------------
__device__ float g_ftdst[BB * NK * 1024];
__device__ float g_V[BB * FF * KH];
__device__ float g_S[BB * NK * HH * 4];

// ---------------- helpers ----------------
// hi/lo bf16x2 split of float pair (f0 in low half)
__device__ __forceinline__ void split_pack(float f0, float f1, uint32_t& hi, uint32_t& lo) {
    uint32_t u0 = __float_as_uint(f0), u1 = __float_as_uint(f1);
    hi = (u1 & 0xFFFF0000u) | (u0 >> 16);
    float r0 = f0 - __uint_as_float(u0 & 0xFFFF0000u);
    float r1 = f1 - __uint_as_float(u1 & 0xFFFF0000u);
    asm("cvt.rn.bf16x2.f32 %0, %1, %2;" : "=r"(lo) : "f"(r1), "f"(r0));
}
__device__ __forceinline__ void mma16816(float* c, const uint32_t* a, uint32_t b0, uint32_t b1) {
    asm volatile(
        "mma.sync.aligned.m16n8k16.row.col.f32.bf16.bf16.f32 "
        "{%0,%1,%2,%3}, {%4,%5,%6,%7}, {%8,%9}, {%0,%1,%2,%3};"
        : "+f"(c[0]), "+f"(c[1]), "+f"(c[2]), "+f"(c[3])
        : "r"(a[0]), "r"(a[1]), "r"(a[2]), "r"(a[3]), "r"(b0), "r"(b1));
}

// ---------------- A1: ft_dst = h0_kp @ W_src (+ zero g_V, g_S) ----------------
#define FT_SMEM_FLOATS (NK * FF + 256 * 65)
__global__ void __launch_bounds__(256) k_ftdst(const float* __restrict__ h0,
                                               const float* __restrict__ W) {
    extern __shared__ float sm[];
    float* hs = sm;
    float* ws = sm + NK * FF;
    int b = blockIdx.y, ct = blockIdx.x;
    if (ct == 0) {
        for (int i = threadIdx.x; i < FF * KH; i += 256) g_V[b * FF * KH + i] = 0.f;
        for (int i = threadIdx.x; i < NK * HH * 4; i += 256) g_S[b * NK * HH * 4 + i] = 0.f;
    }
    for (int i = threadIdx.x; i < NK * FF; i += 256) hs[i] = h0[b * NK * FF + i];
#pragma unroll 8
    for (int i = threadIdx.x; i < 256 * 64; i += 256) {
        int f = i >> 6, c = i & 63;
        ws[f * 65 + c] = W[f * 1024 + ct * 64 + c];
    }
    __syncthreads();
    int cg = threadIdx.x & 63;
    int rgp = threadIdx.x >> 6;
    float acc[5] = {0.f, 0.f, 0.f, 0.f, 0.f};
#pragma unroll 8
    for (int f = 0; f < 256; f++) {
        float w = ws[f * 65 + cg];
#pragma unroll
        for (int q = 0; q < 5; q++) acc[q] += hs[(rgp * 5 + q) * 256 + f] * w;
    }
    int c = ct * 64 + cg;
#pragma unroll
    for (int q = 0; q < 5; q++)
        g_ftdst[(b * NK + rgp * 5 + q) * 1024 + c] = acc[q];
}

// ---------------- A2: V reduction ----------------
#define V_SMEM_FLOATS (64 * 257 + NK * 256)
__global__ void __launch_bounds__(256) k_V(const float* __restrict__ W) {
    extern __shared__ float sm[];
    float* ws2 = sm;
    float* fts2 = sm + 64 * 257;
    int b = blockIdx.y;
    int ft = blockIdx.x >> 2, ds = blockIdx.x & 3;
    int fbase = ft * 64, dbase = ds * 64;
#pragma unroll 4
    for (int i = threadIdx.x; i < 64 * 256; i += 256) {
        int fi = i >> 8, rest = i & 255;
        int h = rest >> 6, dd = rest & 63;
        ws2[fi * 257 + rest] = W[(fbase + fi) * 1024 + h * 256 + dbase + dd];
    }
#pragma unroll 4
    for (int i = threadIdx.x; i < NK * 256; i += 256) {
        int rest = i & 255;
        int h = rest >> 6, dd = rest & 63;
        int k = i >> 8;
        fts2[i] = g_ftdst[b * 20480 + k * 1024 + h * 256 + dbase + dd];
    }
    __syncthreads();
    int fi = threadIdx.x & 63;
    int h  = threadIdx.x >> 6;
    float acc[NK];
#pragma unroll
    for (int j = 0; j < NK; j++) acc[j] = 0.f;
    const float* wp = ws2 + fi * 257 + h * 64;
    const float* fp = fts2 + h * 64;
#pragma unroll 2
    for (int dd = 0; dd < 64; dd++) {
        float w = wp[dd];
#pragma unroll
        for (int j = 0; j < NK; j++) acc[j] += w * fp[j * 256 + dd];
    }
    float* gv = g_V + b * (FF * KH) + (fbase + fi) * KH + h;
#pragma unroll
    for (int j = 0; j < NK; j++)
        atomicAdd(gv + j * 4, acc[j] * 0.0625f);
}

// ---------------- B: HMMA attention  a = h @ V ; exp ; 4 moments ----------------
// grid (16, 8) = 128 CTAs (1 wave), 512 threads (16 warps, 4/SMSP), 256 rows/CTA.
#define SM_BF   0                          // 81920 B: B fragments (hi|lo)
#define SM_XS   81920                      // 4096 B: x positions (float4 x 256)
#define SM_RED  (SM_XS + 4096)             // 20480 B: 16 warps x 320 floats
#define ATTN_SMEM_BYTES (SM_RED + 20480)   // 106496
__global__ void __launch_bounds__(512, 1) k_attn(const float* __restrict__ h_rec,
                                                 const float* __restrict__ x_rec) {
    extern __shared__ char smc[];
    uint32_t* bf = (uint32_t*)(smc + SM_BF);
    float4* xs = (float4*)(smc + SM_XS);
    float* red = (float*)(smc + SM_RED);
    int b = blockIdx.y;
    int tid = threadIdx.x;
    int wid = tid >> 5, lane = tid & 31;
    int g = lane >> 2, tg = lane & 3;
    int rowbase = blockIdx.x * 256;

    // build B fragments in smem directly from g_V
    {
        const float* gV = g_V + b * (FF * KH);
#pragma unroll
        for (int q = 0; q < 20; q++) {
            int i = tid + q * 512;
            int reg = i & 1;
            int l2 = (i >> 1) & 31;
            int knt = i >> 6;
            int nt = knt % 10, ks = knt / 10;
            int g2 = l2 >> 2, t2 = l2 & 3;
            int k = ks * 16 + 2 * t2 + reg * 8;
            int n = nt * 8 + g2;
            float v0 = __ldg(gV + k * 80 + n);
            float v1 = __ldg(gV + (k + 1) * 80 + n);
            uint32_t hi, lo;
            split_pack(v0, v1, hi, lo);
            bf[i] = hi;
            bf[10240 + i] = lo;
        }
    }
    if (tid < 256) {
        const float* xp = x_rec + ((size_t)(b * NR + rowbase + tid)) * 3;
        xs[tid] = make_float4(xp[0], xp[1], xp[2], 0.f);
    }
    __syncthreads();

    // mainloop: direct LDG with 2-deep register prefetch
    const float* hp0 = h_rec + ((size_t)(b * NR + rowbase + wid * 16 + g)) * FF;
    const float* hp1 = hp0 + 8 * FF;
    int cb = 2 * tg;
    float c[10][4];
#pragma unroll
    for (int nt = 0; nt < 10; nt++)
#pragma unroll
        for (int e = 0; e < 4; e++) c[nt][e] = 0.f;

    float2 pA[2][4];
#pragma unroll
    for (int s = 0; s < 2; s++) {
        pA[s][0] = *(const float2*)(hp0 + s * 16 + cb);
        pA[s][1] = *(const float2*)(hp1 + s * 16 + cb);
        pA[s][2] = *(const float2*)(hp0 + s * 16 + cb + 8);
        pA[s][3] = *(const float2*)(hp1 + s * 16 + cb + 8);
    }

#pragma unroll 2
    for (int ks = 0; ks < 16; ks++) {
        uint32_t ah[4], al[4];
#pragma unroll
        for (int j = 0; j < 4; j++)
            split_pack(pA[ks & 1][j].x, pA[ks & 1][j].y, ah[j], al[j]);
        if (ks < 14) {
            int s = ks & 1;
#pragma unroll
            for (int j = 0; j < 4; j++) {
                const float* base = (j & 1) ? hp1 : hp0;
                pA[s][j] = *(const float2*)(base + (ks + 2) * 16 + cb + (j >> 1) * 8);
            }
        }
        const uint32_t* bfh = bf + ks * 640 + lane * 2;
        const uint32_t* bfl = bfh + 10240;
#pragma unroll
        for (int nt = 0; nt < 10; nt++) {
            uint2 bh = *(const uint2*)(bfh + nt * 64);
            uint2 bl = *(const uint2*)(bfl + nt * 64);
            mma16816(c[nt], ah, bh.x, bh.y);
            mma16816(c[nt], ah, bl.x, bl.y);
            mma16816(c[nt], al, bh.x, bh.y);
        }
    }

    // epilogue: per-warp shuffle moment reduction
    {
        float4 x0 = xs[wid * 16 + g];
        float4 x1 = xs[wid * 16 + g + 8];
#pragma unroll
        for (int nt = 0; nt < 10; nt++) {
#pragma unroll
            for (int sub = 0; sub < 2; sub++) {
                float e0 = expf(c[nt][sub]);
                float e1 = expf(c[nt][2 + sub]);
                float v0 = e0 + e1;
                float v1 = e0 * x0.x + e1 * x1.x;
                float v2 = e0 * x0.y + e1 * x1.y;
                float v3 = e0 * x0.z + e1 * x1.z;
#pragma unroll
                for (int d = 16; d >= 4; d >>= 1) {
                    v0 += __shfl_down_sync(0xffffffffu, v0, d);
                    v1 += __shfl_down_sync(0xffffffffu, v1, d);
                    v2 += __shfl_down_sync(0xffffffffu, v2, d);
                    v3 += __shfl_down_sync(0xffffffffu, v3, d);
                }
                if (lane < 4) {
                    int cc = nt * 8 + 2 * lane + sub;
                    float* rp = red + wid * 320 + cc * 4;
                    rp[0] = v0; rp[1] = v1; rp[2] = v2; rp[3] = v3;
                }
            }
        }
    }
    __syncthreads();
    for (int v = tid; v < 320; v += 512) {
        float sum = 0.f;
#pragma unroll
        for (int w2 = 0; w2 < 16; w2++) sum += red[w2 * 320 + v];
        atomicAdd(&g_S[b * 320 + v], sum);
    }
}

// ---------------- tail: 2 independent keypoints per 512-thread block ----------------
// grid 80 = 1 wave, 16 warps/SM. half = tid>>8 picks the keypoint; halves never
// share data, only the (stage-identical) __syncthreads schedule.
__global__ void __launch_bounds__(512) k_tail(const float* __restrict__ x_rec,
                                              const float* __restrict__ h_rec,
                                              const float* __restrict__ W_mlp,
                                              const float* __restrict__ b_mlp,
                                              const float* __restrict__ gamma,
                                              const float* __restrict__ beta,
                                              float* __restrict__ out) {
    __shared__ float sd[2][256 * KNN];
    __shared__ int   si[2][256 * KNN];
    __shared__ float kpos[2][3];
    __shared__ float hm[2][FF];
    __shared__ float dk8[2][KNN];
    __shared__ int   id8[2][KNN];
    __shared__ float rbuf[2][16];
    __shared__ float mv[2][2];
    int half = threadIdx.x >> 8;
    int t = threadIdx.x & 255;
    int bk = blockIdx.x * 2 + half;
    int b = bk / NK;

    if (t == 0) {
        float p0 = 0.f, p1 = 0.f, p2 = 0.f;
#pragma unroll
        for (int h = 0; h < HH; h++) {
            const float* S = g_S + bk * 16 + h * 4;
            float inv = 1.f / S[0];
            p0 += S[1] * inv; p1 += S[2] * inv; p2 += S[3] * inv;
        }
        p0 *= 0.25f; p1 *= 0.25f; p2 *= 0.25f;
        kpos[half][0] = p0; kpos[half][1] = p1; kpos[half][2] = p2;
        out[bk * 3 + 0] = p0; out[bk * 3 + 1] = p1; out[bk * 3 + 2] = p2;
    }
    __syncthreads();
    float px = kpos[half][0], py = kpos[half][1], pz = kpos[half][2];

    float bd[KNN]; int bi[KNN];
#pragma unroll
    for (int j = 0; j < KNN; j++) { bd[j] = 3.4e38f; bi[j] = 0x7fffffff; }
    const float* xb = x_rec + (size_t)b * NR * 3;
#pragma unroll 1
    for (int base = 0; base < NR; base += 1024) {
        float d2v[4];
#pragma unroll
        for (int u = 0; u < 4; u++) {
            int r = base + u * 256 + t;
            float dx = xb[r * 3 + 0] - px;
            float dy = xb[r * 3 + 1] - py;
            float dz = xb[r * 3 + 2] - pz;
            d2v[u] = dx * dx + dy * dy + dz * dz;
        }
#pragma unroll
        for (int u = 0; u < 4; u++) {
            float d2 = d2v[u];
            if (d2 < bd[KNN - 1]) {
                int r = base + u * 256 + t;
                int p = KNN - 1;
                while (p > 0 && d2 < bd[p - 1]) { bd[p] = bd[p - 1]; bi[p] = bi[p - 1]; p--; }
                bd[p] = d2; bi[p] = r;
            }
        }
    }
#pragma unroll
    for (int j = 0; j < KNN; j++) { sd[half][t * KNN + j] = bd[j]; si[half][t * KNN + j] = bi[j]; }
    for (int stride = 128; stride >= 1; stride >>= 1) {
        __syncthreads();
        if (t < stride) {
            float od[KNN]; int oi[KNN];
            int ia = 0, ib = 0;
#pragma unroll
            for (int o = 0; o < KNN; o++) {
                float da = sd[half][t * KNN + ia], db = sd[half][(t + stride) * KNN + ib];
                int xa = si[half][t * KNN + ia], xb2 = si[half][(t + stride) * KNN + ib];
                bool ta = (da < db) || (da == db && xa < xb2);
                if (ta) { od[o] = da; oi[o] = xa; ia++; }
                else    { od[o] = db; oi[o] = xb2; ib++; }
            }
#pragma unroll
            for (int o = 0; o < KNN; o++) { sd[half][t * KNN + o] = od[o]; si[half][t * KNN + o] = oi[o]; }
        }
    }
    __syncthreads();
    if (t < KNN) { dk8[half][t] = sqrtf(sd[half][t]); id8[half][t] = si[half][t]; }
    __syncthreads();

    int j = t;
    float a = 0.f;
#pragma unroll
    for (int tt = 0; tt < KNN; tt++)
        a += h_rec[((size_t)b * NR + id8[half][tt]) * FF + j];
    hm[half][j] = a * 0.125f;
    __syncthreads();

    float y = b_mlp[j];
#pragma unroll 16
    for (int i = 0; i < FF; i++) y += hm[half][i] * W_mlp[i * FF + j];
#pragma unroll
    for (int tt = 0; tt < KNN; tt++) y += dk8[half][tt] * W_mlp[(FF + tt) * FF + j];
    y = y / (1.f + expf(-y));

    float s1 = y, s2 = y * y;
#pragma unroll
    for (int d = 16; d; d >>= 1) {
        s1 += __shfl_down_sync(0xffffffffu, s1, d);
        s2 += __shfl_down_sync(0xffffffffu, s2, d);
    }
    int lane = t & 31, w = t >> 5;
    if (lane == 0) { rbuf[half][w] = s1; rbuf[half][8 + w] = s2; }
    __syncthreads();
    if (t == 0) {
        float sa = 0.f, sb = 0.f;
#pragma unroll
        for (int w2 = 0; w2 < 8; w2++) { sa += rbuf[half][w2]; sb += rbuf[half][8 + w2]; }
        float mu = sa * (1.f / 256.f);
        mv[half][0] = mu;
        mv[half][1] = sb * (1.f / 256.f) - mu * mu;
    }
    __syncthreads();
    float mu = mv[half][0];
    float inv = rsqrtf(mv[half][1] + 1e-5f);
    out[BB * NK * 3 + bk * FF + j] = (y - mu) * inv * gamma[j] + beta[j];
}

// ---------------- launch ----------------
extern "C" void kernel_launch(void* const* d_in, const int* in_sizes, int n_in,
                              void* d_out, int out_size) {
    const float* h_rec = (const float*)d_in[0];
    const float* x_rec = (const float*)d_in[1];
    const float* h0_kp = (const float*)d_in[2];
    const float* W_src = (const float*)d_in[3];
    const float* W_mlp = (const float*)d_in[4];
    const float* b_mlp = (const float*)d_in[5];
    const float* gamma = (const float*)d_in[6];
    const float* beta  = (const float*)d_in[7];
    float* out = (float*)d_out;

    const int v_smem = V_SMEM_FLOATS * 4;
    const int ft_smem = FT_SMEM_FLOATS * 4;
    cudaFuncSetAttribute(k_attn, cudaFuncAttributeMaxDynamicSharedMemorySize, ATTN_SMEM_BYTES);
    cudaFuncSetAttribute(k_V, cudaFuncAttributeMaxDynamicSharedMemorySize, v_smem);
    cudaFuncSetAttribute(k_ftdst, cudaFuncAttributeMaxDynamicSharedMemorySize, ft_smem);

    k_ftdst<<<dim3(16, BB), 256, ft_smem>>>(h0_kp, W_src);        // launch 1 (+zero g_V,g_S)
    k_V<<<dim3(16, BB), 256, v_smem>>>(W_src);                    // launch 2
    k_attn<<<dim3(16, BB), 512, ATTN_SMEM_BYTES>>>(h_rec, x_rec); // launch 3
    k_tail<<<BB * NK / 2, 512>>>(x_rec, h_rec, W_mlp, b_mlp, gamma, beta, out);  // launch 4 -> profiled
}

// round 15
// speedup vs baseline: 1.7828x; 1.0574x over previous
#include <cuda_runtime.h>
#include <cuda_bf16.h>
#include <cstdint>

// ---------------- problem constants ----------------
#define BB   8
#define NR   4096
#define NK   20
#define FF   256
#define HH   4
#define KH   80
#define KNN  8

// ---------------- device scratch ----------------
__device__ float g_ftdst[BB * NK * 1024];
__device__ float g_V[BB * FF * KH];
__device__ float g_S[BB * NK * HH * 4];

// ---------------- helpers ----------------
__device__ __forceinline__ void split_pack(float f0, float f1, uint32_t& hi, uint32_t& lo) {
    uint32_t u0 = __float_as_uint(f0), u1 = __float_as_uint(f1);
    hi = (u1 & 0xFFFF0000u) | (u0 >> 16);
    float r0 = f0 - __uint_as_float(u0 & 0xFFFF0000u);
    float r1 = f1 - __uint_as_float(u1 & 0xFFFF0000u);
    asm("cvt.rn.bf16x2.f32 %0, %1, %2;" : "=r"(lo) : "f"(r1), "f"(r0));
}
__device__ __forceinline__ void mma16816(float* c, const uint32_t* a, uint32_t b0, uint32_t b1) {
    asm volatile(
        "mma.sync.aligned.m16n8k16.row.col.f32.bf16.bf16.f32 "
        "{%0,%1,%2,%3}, {%4,%5,%6,%7}, {%8,%9}, {%0,%1,%2,%3};"
        : "+f"(c[0]), "+f"(c[1]), "+f"(c[2]), "+f"(c[3])
        : "r"(a[0]), "r"(a[1]), "r"(a[2]), "r"(a[3]), "r"(b0), "r"(b1));
}

// ---------------- A1: ft_dst = h0_kp @ W_src (+ zero g_V, g_S) ----------------
#define FT_SMEM_FLOATS (NK * FF + 256 * 65)
__global__ void __launch_bounds__(256) k_ftdst(const float* __restrict__ h0,
                                               const float* __restrict__ W) {
    extern __shared__ float sm[];
    float* hs = sm;
    float* ws = sm + NK * FF;
    int b = blockIdx.y, ct = blockIdx.x;
    if (ct == 0) {
        for (int i = threadIdx.x; i < FF * KH; i += 256) g_V[b * FF * KH + i] = 0.f;
        for (int i = threadIdx.x; i < NK * HH * 4; i += 256) g_S[b * NK * HH * 4 + i] = 0.f;
    }
    for (int i = threadIdx.x; i < NK * FF; i += 256) hs[i] = h0[b * NK * FF + i];
#pragma unroll 8
    for (int i = threadIdx.x; i < 256 * 64; i += 256) {
        int f = i >> 6, c = i & 63;
        ws[f * 65 + c] = W[f * 1024 + ct * 64 + c];
    }
    __syncthreads();
    int cg = threadIdx.x & 63;
    int rgp = threadIdx.x >> 6;
    float acc[5] = {0.f, 0.f, 0.f, 0.f, 0.f};
#pragma unroll 8
    for (int f = 0; f < 256; f++) {
        float w = ws[f * 65 + cg];
#pragma unroll
        for (int q = 0; q < 5; q++) acc[q] += hs[(rgp * 5 + q) * 256 + f] * w;
    }
    int c = ct * 64 + cg;
#pragma unroll
    for (int q = 0; q < 5; q++)
        g_ftdst[(b * NK + rgp * 5 + q) * 1024 + c] = acc[q];
}

// ---------------- A2: V reduction ----------------
#define V_SMEM_FLOATS (64 * 257 + NK * 256)
__global__ void __launch_bounds__(256) k_V(const float* __restrict__ W) {
    extern __shared__ float sm[];
    float* ws2 = sm;
    float* fts2 = sm + 64 * 257;
    int b = blockIdx.y;
    int ft = blockIdx.x >> 2, ds = blockIdx.x & 3;
    int fbase = ft * 64, dbase = ds * 64;
#pragma unroll 4
    for (int i = threadIdx.x; i < 64 * 256; i += 256) {
        int fi = i >> 8, rest = i & 255;
        int h = rest >> 6, dd = rest & 63;
        ws2[fi * 257 + rest] = W[(fbase + fi) * 1024 + h * 256 + dbase + dd];
    }
#pragma unroll 4
    for (int i = threadIdx.x; i < NK * 256; i += 256) {
        int rest = i & 255;
        int h = rest >> 6, dd = rest & 63;
        int k = i >> 8;
        fts2[i] = g_ftdst[b * 20480 + k * 1024 + h * 256 + dbase + dd];
    }
    __syncthreads();
    int fi = threadIdx.x & 63;
    int h  = threadIdx.x >> 6;
    float acc[NK];
#pragma unroll
    for (int j = 0; j < NK; j++) acc[j] = 0.f;
    const float* wp = ws2 + fi * 257 + h * 64;
    const float* fp = fts2 + h * 64;
#pragma unroll 2
    for (int dd = 0; dd < 64; dd++) {
        float w = wp[dd];
#pragma unroll
        for (int j = 0; j < NK; j++) acc[j] += w * fp[j * 256 + dd];
    }
    float* gv = g_V + b * (FF * KH) + (fbase + fi) * KH + h;
#pragma unroll
    for (int j = 0; j < NK; j++)
        atomicAdd(gv + j * 4, acc[j] * 0.0625f);
}

// ---------------- B: HMMA attention ----------------
#define SM_BF   0
#define SM_XS   81920
#define SM_RED  (SM_XS + 4096)
#define ATTN_SMEM_BYTES (SM_RED + 20480)   // 106496
__global__ void __launch_bounds__(512, 1) k_attn(const float* __restrict__ h_rec,
                                                 const float* __restrict__ x_rec) {
    extern __shared__ char smc[];
    uint32_t* bf = (uint32_t*)(smc + SM_BF);
    float4* xs = (float4*)(smc + SM_XS);
    float* red = (float*)(smc + SM_RED);
    int b = blockIdx.y;
    int tid = threadIdx.x;
    int wid = tid >> 5, lane = tid & 31;
    int g = lane >> 2, tg = lane & 3;
    int rowbase = blockIdx.x * 256;

    {
        const float* gV = g_V + b * (FF * KH);
#pragma unroll
        for (int q = 0; q < 20; q++) {
            int i = tid + q * 512;
            int reg = i & 1;
            int l2 = (i >> 1) & 31;
            int knt = i >> 6;
            int nt = knt % 10, ks = knt / 10;
            int g2 = l2 >> 2, t2 = l2 & 3;
            int k = ks * 16 + 2 * t2 + reg * 8;
            int n = nt * 8 + g2;
            float v0 = __ldg(gV + k * 80 + n);
            float v1 = __ldg(gV + (k + 1) * 80 + n);
            uint32_t hi, lo;
            split_pack(v0, v1, hi, lo);
            bf[i] = hi;
            bf[10240 + i] = lo;
        }
    }
    if (tid < 256) {
        const float* xp = x_rec + ((size_t)(b * NR + rowbase + tid)) * 3;
        xs[tid] = make_float4(xp[0], xp[1], xp[2], 0.f);
    }
    __syncthreads();

    const float* hp0 = h_rec + ((size_t)(b * NR + rowbase + wid * 16 + g)) * FF;
    const float* hp1 = hp0 + 8 * FF;
    int cb = 2 * tg;
    float c[10][4];
#pragma unroll
    for (int nt = 0; nt < 10; nt++)
#pragma unroll
        for (int e = 0; e < 4; e++) c[nt][e] = 0.f;

    float2 pA[2][4];
#pragma unroll
    for (int s = 0; s < 2; s++) {
        pA[s][0] = *(const float2*)(hp0 + s * 16 + cb);
        pA[s][1] = *(const float2*)(hp1 + s * 16 + cb);
        pA[s][2] = *(const float2*)(hp0 + s * 16 + cb + 8);
        pA[s][3] = *(const float2*)(hp1 + s * 16 + cb + 8);
    }

#pragma unroll 2
    for (int ks = 0; ks < 16; ks++) {
        uint32_t ah[4], al[4];
#pragma unroll
        for (int j = 0; j < 4; j++)
            split_pack(pA[ks & 1][j].x, pA[ks & 1][j].y, ah[j], al[j]);
        if (ks < 14) {
            int s = ks & 1;
#pragma unroll
            for (int j = 0; j < 4; j++) {
                const float* base = (j & 1) ? hp1 : hp0;
                pA[s][j] = *(const float2*)(base + (ks + 2) * 16 + cb + (j >> 1) * 8);
            }
        }
        const uint32_t* bfh = bf + ks * 640 + lane * 2;
        const uint32_t* bfl = bfh + 10240;
#pragma unroll
        for (int nt = 0; nt < 10; nt++) {
            uint2 bh = *(const uint2*)(bfh + nt * 64);
            uint2 bl = *(const uint2*)(bfl + nt * 64);
            mma16816(c[nt], ah, bh.x, bh.y);
            mma16816(c[nt], ah, bl.x, bl.y);
            mma16816(c[nt], al, bh.x, bh.y);
        }
    }

    {
        float4 x0 = xs[wid * 16 + g];
        float4 x1 = xs[wid * 16 + g + 8];
#pragma unroll
        for (int nt = 0; nt < 10; nt++) {
#pragma unroll
            for (int sub = 0; sub < 2; sub++) {
                float e0 = expf(c[nt][sub]);
                float e1 = expf(c[nt][2 + sub]);
                float v0 = e0 + e1;
                float v1 = e0 * x0.x + e1 * x1.x;
                float v2 = e0 * x0.y + e1 * x1.y;
                float v3 = e0 * x0.z + e1 * x1.z;
#pragma unroll
                for (int d = 16; d >= 4; d >>= 1) {
                    v0 += __shfl_down_sync(0xffffffffu, v0, d);
                    v1 += __shfl_down_sync(0xffffffffu, v1, d);
                    v2 += __shfl_down_sync(0xffffffffu, v2, d);
                    v3 += __shfl_down_sync(0xffffffffu, v3, d);
                }
                if (lane < 4) {
                    int cc = nt * 8 + 2 * lane + sub;
                    float* rp = red + wid * 320 + cc * 4;
                    rp[0] = v0; rp[1] = v1; rp[2] = v2; rp[3] = v3;
                }
            }
        }
    }
    __syncthreads();
    for (int v = tid; v < 320; v += 512) {
        float sum = 0.f;
#pragma unroll
        for (int w2 = 0; w2 < 16; w2++) sum += red[w2 * 320 + v];
        atomicAdd(&g_S[b * 320 + v], sum);
    }
}

// ---------------- tail: 2 independent keypoints per 512-thread block ----------------
// Register-resident top-8 (constant-index bubble insert) + padded merge tree.
#define PAD 9
__global__ void __launch_bounds__(512) k_tail(const float* __restrict__ x_rec,
                                              const float* __restrict__ h_rec,
                                              const float* __restrict__ W_mlp,
                                              const float* __restrict__ b_mlp,
                                              const float* __restrict__ gamma,
                                              const float* __restrict__ beta,
                                              float* __restrict__ out) {
    __shared__ float sd[2][256 * PAD];
    __shared__ int   si[2][256 * PAD];
    __shared__ float kpos[2][3];
    __shared__ float hm[2][FF];
    __shared__ float dk8[2][KNN];
    __shared__ int   id8[2][KNN];
    __shared__ float rbuf[2][16];
    __shared__ float mv[2][2];
    int half = threadIdx.x >> 8;
    int t = threadIdx.x & 255;
    int bk = blockIdx.x * 2 + half;
    int b = bk / NK;

    if (t == 0) {
        float p0 = 0.f, p1 = 0.f, p2 = 0.f;
#pragma unroll
        for (int h = 0; h < HH; h++) {
            const float* S = g_S + bk * 16 + h * 4;
            float inv = 1.f / S[0];
            p0 += S[1] * inv; p1 += S[2] * inv; p2 += S[3] * inv;
        }
        p0 *= 0.25f; p1 *= 0.25f; p2 *= 0.25f;
        kpos[half][0] = p0; kpos[half][1] = p1; kpos[half][2] = p2;
        out[bk * 3 + 0] = p0; out[bk * 3 + 1] = p1; out[bk * 3 + 2] = p2;
    }
    __syncthreads();
    float px = kpos[half][0], py = kpos[half][1], pz = kpos[half][2];

    // register-resident top-8 (constant indices only)
    float bd[KNN]; int bi[KNN];
#pragma unroll
    for (int j = 0; j < KNN; j++) { bd[j] = 3.4e38f; bi[j] = 0x7fffffff; }
    const float* xb = x_rec + (size_t)b * NR * 3;
#pragma unroll 1
    for (int base = 0; base < NR; base += 1024) {
        float d2v[4];
#pragma unroll
        for (int u = 0; u < 4; u++) {
            int r = base + u * 256 + t;
            float dx = xb[r * 3 + 0] - px;
            float dy = xb[r * 3 + 1] - py;
            float dz = xb[r * 3 + 2] - pz;
            d2v[u] = dx * dx + dy * dy + dz * dz;
        }
#pragma unroll
        for (int u = 0; u < 4; u++) {
            float d2 = d2v[u];
            if (d2 < bd[KNN - 1]) {
                bd[KNN - 1] = d2;
                bi[KNN - 1] = base + u * 256 + t;
                // single bubble pass, constant indices -> predicated SELs
#pragma unroll
                for (int j = KNN - 1; j >= 1; j--) {
                    bool sw = bd[j] < bd[j - 1];
                    float td = sw ? bd[j - 1] : bd[j];
                    float th = sw ? bd[j] : bd[j - 1];
                    int   ti = sw ? bi[j - 1] : bi[j];
                    int   th2 = sw ? bi[j] : bi[j - 1];
                    bd[j] = td; bd[j - 1] = th;
                    bi[j] = ti; bi[j - 1] = th2;
                }
            }
        }
    }
#pragma unroll
    for (int j = 0; j < KNN; j++) { sd[half][t * PAD + j] = bd[j]; si[half][t * PAD + j] = bi[j]; }
    for (int stride = 128; stride >= 1; stride >>= 1) {
        __syncthreads();
        if (t < stride) {
            float od[KNN]; int oi[KNN];
            int ia = 0, ib = 0;
#pragma unroll
            for (int o = 0; o < KNN; o++) {
                float da = sd[half][t * PAD + ia], db = sd[half][(t + stride) * PAD + ib];
                int xa = si[half][t * PAD + ia], xb2 = si[half][(t + stride) * PAD + ib];
                bool ta = (da < db) || (da == db && xa < xb2);
                if (ta) { od[o] = da; oi[o] = xa; ia++; }
                else    { od[o] = db; oi[o] = xb2; ib++; }
            }
#pragma unroll
            for (int o = 0; o < KNN; o++) { sd[half][t * PAD + o] = od[o]; si[half][t * PAD + o] = oi[o]; }
        }
    }
    __syncthreads();
    if (t < KNN) { dk8[half][t] = sqrtf(sd[half][t]); id8[half][t] = si[half][t]; }
    __syncthreads();

    int j = t;
    float a = 0.f;
#pragma unroll
    for (int tt = 0; tt < KNN; tt++)
        a += h_rec[((size_t)b * NR + id8[half][tt]) * FF + j];
    hm[half][j] = a * 0.125f;
    __syncthreads();

    float y = b_mlp[j];
#pragma unroll 16
    for (int i = 0; i < FF; i++) y += hm[half][i] * W_mlp[i * FF + j];
#pragma unroll
    for (int tt = 0; tt < KNN; tt++) y += dk8[half][tt] * W_mlp[(FF + tt) * FF + j];
    y = y / (1.f + expf(-y));

    float s1 = y, s2 = y * y;
#pragma unroll
    for (int d = 16; d; d >>= 1) {
        s1 += __shfl_down_sync(0xffffffffu, s1, d);
        s2 += __shfl_down_sync(0xffffffffu, s2, d);
    }
    int lane = t & 31, w = t >> 5;
    if (lane == 0) { rbuf[half][w] = s1; rbuf[half][8 + w] = s2; }
    __syncthreads();
    if (t == 0) {
        float sa = 0.f, sb = 0.f;
#pragma unroll
        for (int w2 = 0; w2 < 8; w2++) { sa += rbuf[half][w2]; sb += rbuf[half][8 + w2]; }
        float mu = sa * (1.f / 256.f);
        mv[half][0] = mu;
        mv[half][1] = sb * (1.f / 256.f) - mu * mu;
    }
    __syncthreads();
    float mu = mv[half][0];
    float inv = rsqrtf(mv[half][1] + 1e-5f);
    out[BB * NK * 3 + bk * FF + j] = (y - mu) * inv * gamma[j] + beta[j];
}

// ---------------- launch ----------------
extern "C" void kernel_launch(void* const* d_in, const int* in_sizes, int n_in,
                              void* d_out, int out_size) {
    const float* h_rec = (const float*)d_in[0];
    const float* x_rec = (const float*)d_in[1];
    const float* h0_kp = (const float*)d_in[2];
    const float* W_src = (const float*)d_in[3];
    const float* W_mlp = (const float*)d_in[4];
    const float* b_mlp = (const float*)d_in[5];
    const float* gamma = (const float*)d_in[6];
    const float* beta  = (const float*)d_in[7];
    float* out = (float*)d_out;

    const int v_smem = V_SMEM_FLOATS * 4;
    const int ft_smem = FT_SMEM_FLOATS * 4;
    cudaFuncSetAttribute(k_attn, cudaFuncAttributeMaxDynamicSharedMemorySize, ATTN_SMEM_BYTES);
    cudaFuncSetAttribute(k_V, cudaFuncAttributeMaxDynamicSharedMemorySize, v_smem);
    cudaFuncSetAttribute(k_ftdst, cudaFuncAttributeMaxDynamicSharedMemorySize, ft_smem);

    k_ftdst<<<dim3(16, BB), 256, ft_smem>>>(h0_kp, W_src);        // launch 1 (+zero g_V,g_S)
    k_V<<<dim3(16, BB), 256, v_smem>>>(W_src);                    // launch 2
    k_attn<<<dim3(16, BB), 512, ATTN_SMEM_BYTES>>>(h_rec, x_rec); // launch 3
    k_tail<<<BB * NK / 2, 512>>>(x_rec, h_rec, W_mlp, b_mlp, gamma, beta, out);  // launch 4 -> profiled
}